// round 8
// baseline (speedup 1.0000x reference)
#include <cuda_runtime.h>
#include <cuda_fp16.h>
#include <stdint.h>

// ---------------- problem constants ----------------
#define NUM_EXEC   50
#define MAXB       60000
#define MAXT       (MAXB * NUM_EXEC)

typedef unsigned long long ull;

// ---------------- device scratch ----------------
__device__ int   g_nsel[MAXB];
__device__ int   g_blocksum[512];
__device__ int   g_rowjob[MAXT];
__device__ float g_base1[(size_t)MAXB * 64];
// prepped weight blob (exact smem image):
//  [0,8192)      W2^T hi  fp16 [n=64][k=64], 128B rows, XOR-16B swizzle
//  [8192,16384)  W2^T lo  (fp16 residual)
//  [16384,20480) W3^T hi  [n=32][k=64]
//  [20480,24576) W3^T lo
//  [24576,25600) fp32 smalls: W1L[64] b2[64] b3[32] W4[32] b4[1]
__device__ __align__(16) unsigned char g_wblob[25600];

// ---------------- helpers ----------------
__device__ __forceinline__ ull fma2(ull a, ull b, ull c) {
    ull d;
    asm("fma.rn.f32x2 %0, %1, %2, %3;" : "=l"(d) : "l"(a), "l"(b), "l"(c));
    return d;
}
__device__ __forceinline__ ull pack2(float a, float b) {
    ull r;
    asm("mov.b64 %0, {%1,%2};" : "=l"(r) : "f"(a), "f"(b));
    return r;
}
__device__ __forceinline__ void unpack2(ull v, float& a, float& b) {
    asm("mov.b64 {%0,%1}, %2;" : "=f"(a), "=f"(b) : "l"(v));
}
__device__ __forceinline__ uint32_t smem_u32(const void* p) {
    uint32_t a;
    asm("{ .reg .u64 t; cvta.to.shared.u64 t, %1; cvt.u32.u64 %0, t; }" : "=r"(a) : "l"(p));
    return a;
}
// pack (lo_elem, hi_elem) -> f16x2, lo_elem in low 16 bits
__device__ __forceinline__ uint32_t packh2(float lov, float hiv) {
    uint32_t r;
    asm("cvt.rn.f16x2.f32 %0, %1, %2;" : "=r"(r) : "f"(hiv), "f"(lov));
    return r;
}
__device__ __forceinline__ void ldmatrix4(uint32_t& a0, uint32_t& a1, uint32_t& a2,
                                          uint32_t& a3, uint32_t addr) {
    asm volatile("ldmatrix.sync.aligned.m8n8.x4.shared.b16 {%0,%1,%2,%3}, [%4];"
                 : "=r"(a0), "=r"(a1), "=r"(a2), "=r"(a3) : "r"(addr));
}
__device__ __forceinline__ void mma16816(float& d0, float& d1, float& d2, float& d3,
                                         uint32_t a0, uint32_t a1, uint32_t a2, uint32_t a3,
                                         uint32_t b0, uint32_t b1) {
    asm volatile("mma.sync.aligned.m16n8k16.row.col.f32.f16.f16.f32 "
                 "{%0,%1,%2,%3}, {%4,%5,%6,%7}, {%8,%9}, {%0,%1,%2,%3};"
                 : "+f"(d0), "+f"(d1), "+f"(d2), "+f"(d3)
                 : "r"(a0), "r"(a1), "r"(a2), "r"(a3), "r"(b0), "r"(b1));
}
// XOR-16B swizzle for 128B rows
__device__ __host__ __forceinline__ uint32_t sw128(uint32_t b) {
    return b ^ ((b >> 3) & 0x70);
}

// ================= prologue 1: nsel gather + per-256 block sums =================
__global__ void k_p1(const int* __restrict__ job_indices,
                     const int* __restrict__ num_exec_acts, int J) {
    __shared__ int s[256];
    int j = blockIdx.x * 256 + threadIdx.x;
    int v = 0;
    if (j < J) { v = num_exec_acts[job_indices[j]]; g_nsel[j] = v; }
    s[threadIdx.x] = v;
    __syncthreads();
    #pragma unroll
    for (int o = 128; o > 0; o >>= 1) {
        if (threadIdx.x < o) s[threadIdx.x] += s[threadIdx.x + o];
        __syncthreads();
    }
    if (threadIdx.x == 0) g_blocksum[blockIdx.x] = s[0];
}

// ================= prologue 2: exclusive scan of block sums =================
__global__ void k_scan(int nblocks) {
    __shared__ int s[512];
    int tid = threadIdx.x;
    int v = (tid < nblocks) ? g_blocksum[tid] : 0;
    s[tid] = v;
    __syncthreads();
    for (int o = 1; o < 512; o <<= 1) {
        int t = (tid >= o) ? s[tid - o] : 0;
        __syncthreads();
        s[tid] += t;
        __syncthreads();
    }
    if (tid < nblocks) g_blocksum[tid] = s[tid] - v;
}

// ================= prologue 3: per-job start + row->job fill =================
__global__ void k_p3(int J) {
    __shared__ int s[256];
    int tid = threadIdx.x;
    int j = blockIdx.x * 256 + tid;
    int v = (j < J) ? g_nsel[j] : 0;
    s[tid] = v;
    __syncthreads();
    for (int o = 1; o < 256; o <<= 1) {
        int t = (tid >= o) ? s[tid - o] : 0;
        __syncthreads();
        s[tid] += t;
        __syncthreads();
    }
    if (j < J) {
        int start = (s[tid] - v) + g_blocksum[blockIdx.x];
        for (int k = 0; k < v; k++) g_rowjob[start + k] = j;
    }
}

// ================= prologue 4: base1 — 64 jobs per block, low-reg body ==========
__global__ void __launch_bounds__(256) k_base1(
    const float* __restrict__ x, const float* __restrict__ h_dag,
    const float* __restrict__ h_glob,
    const int* __restrict__ ptr, const int* __restrict__ jidx,
    const float* __restrict__ W1, const float* __restrict__ b1, int J) {
    __shared__ __align__(16) float sW1[35 * 64];
    __shared__ __align__(16) float sB1[64];
    for (int i = threadIdx.x; i < 35 * 64; i += blockDim.x) sW1[i] = W1[i];
    for (int i = threadIdx.x; i < 64; i += blockDim.x)      sB1[i] = b1[i];
    __syncthreads();

    const int warp = threadIdx.x >> 5;
    const int lane = threadIdx.x & 31;
    const int jbase = blockIdx.x * 64 + warp;

    #pragma unroll 1
    for (int it = 0; it < 8; it++) {
        int j = jbase + it * 8;
        if (j >= J) break;

        int ji = jidx[j];
        long long node = (long long)ptr[ji];
        const float* xr = x + node * 5;
        const float* hd = h_dag + (long long)ji * 16;
        const float* hg = h_glob + (long long)j * 16;

        ull acc = pack2(sB1[2 * lane], sB1[2 * lane + 1]);
        #pragma unroll
        for (int i = 0; i < 3; i++) {
            float v = xr[i];
            acc = fma2(pack2(v, v), *(const ull*)&sW1[i * 64 + 2 * lane], acc);
        }
        #pragma unroll
        for (int i = 0; i < 16; i++) {
            float v = hd[i];
            acc = fma2(pack2(v, v), *(const ull*)&sW1[(3 + i) * 64 + 2 * lane], acc);
        }
        #pragma unroll
        for (int i = 0; i < 16; i++) {
            float v = hg[i];
            acc = fma2(pack2(v, v), *(const ull*)&sW1[(19 + i) * 64 + 2 * lane], acc);
        }
        float a, b;
        unpack2(acc, a, b);
        float* dst = g_base1 + (size_t)j * 64 + 2 * lane;
        dst[0] = a;
        dst[1] = b;
    }
}

// ================= prologue 5: weight prep (transpose + fp16 split + swizzle) =====
__global__ void k_wprep(const float* __restrict__ W1, const float* __restrict__ W2,
                        const float* __restrict__ b2, const float* __restrict__ W3,
                        const float* __restrict__ b3, const float* __restrict__ W4,
                        const float* __restrict__ b4) {
    int tid = blockIdx.x * blockDim.x + threadIdx.x;
    if (tid < 4096) {                 // W2^T: [n][k] = W2[k][n]
        int n = tid >> 6, k = tid & 63;
        float w = W2[k * 64 + n];
        __half h = __float2half_rn(w);
        __half l = __float2half_rn(w - __half2float(h));
        uint32_t sw = sw128((uint32_t)(n * 128 + 2 * k));
        *(__half*)(g_wblob + sw)        = h;
        *(__half*)(g_wblob + 8192 + sw) = l;
    } else if (tid < 6144) {          // W3^T: [n][k] = W3[k][n]
        int e = tid - 4096;
        int n = e >> 6, k = e & 63;
        float w = W3[k * 32 + n];
        __half h = __float2half_rn(w);
        __half l = __float2half_rn(w - __half2float(h));
        uint32_t sw = sw128((uint32_t)(n * 128 + 2 * k));
        *(__half*)(g_wblob + 16384 + sw) = h;
        *(__half*)(g_wblob + 20480 + sw) = l;
    } else if (tid < 6144 + 256) {
        int i = tid - 6144;
        float* s = (float*)(g_wblob + 24576);
        if (i < 64)       s[i] = W1[35 * 64 + i];
        else if (i < 128) s[i] = b2[i - 64];
        else if (i < 160) s[i] = b3[i - 128];
        else if (i < 192) s[i] = W4[i - 160];
        else if (i == 192) s[192] = b4[0];
    }
}

// ================= main: mma.sync (fp16 2-product) fused MLP, 128 rows/CTA ==========
// dyn smem: [0,25600) weight blob image; [25600,41984) A fp16 [128][128B] swizzled
#define SM_A    25600
#define KM_SMEM 41984

__global__ void __launch_bounds__(128, 4) k_mlp_mma(
    const int* __restrict__ exec_act_idx, float* __restrict__ out, int T) {

    extern __shared__ unsigned char sm8[];
    const uint32_t smb = smem_u32(sm8);
    const float* smallf = (const float*)(sm8 + 24576);

    const int tid  = threadIdx.x;
    const int warp = tid >> 5;
    const int lane = tid & 31;
    const int q    = lane & 3;        // quad index
    const int qr   = lane >> 2;       // row-within-8
    const int rbase = warp * 32;
    const int lg   = lane >> 3;       // ldmatrix group 0..3
    const int lr   = lane & 7;        // row within group

    // ---- copy prepped weights + smalls (25600 B) ----
    {
        const uint4* src = (const uint4*)g_wblob;
        uint4* dst = (uint4*)sm8;
        #pragma unroll
        for (int it = 0; it < 13; it++) {
            int i = tid + it * 128;
            if (i < 1600) dst[i] = src[i];
        }
    }
    __syncthreads();

    const int t  = blockIdx.x * 128 + tid;
    const int tt = (t < T) ? t : (T - 1);

    // ---- layer 1: h1 = relu(base1[j] + kf*W1L) -> fp16 -> smem A ----
    {
        int j   = g_rowjob[tt];
        float kf = (float)exec_act_idx[tt] * (1.0f / (float)NUM_EXEC);
        const float4* bp = (const float4*)(g_base1 + (size_t)j * 64);
        const int row = tid;
        #pragma unroll
        for (int c = 0; c < 8; c++) {               // 8 chunks x 8 values = 64
            float4 va = bp[2 * c];
            float4 vb = bp[2 * c + 1];
            float v0 = fmaxf(fmaf(kf, smallf[8 * c + 0], va.x), 0.0f);
            float v1 = fmaxf(fmaf(kf, smallf[8 * c + 1], va.y), 0.0f);
            float v2 = fmaxf(fmaf(kf, smallf[8 * c + 2], va.z), 0.0f);
            float v3 = fmaxf(fmaf(kf, smallf[8 * c + 3], va.w), 0.0f);
            float v4 = fmaxf(fmaf(kf, smallf[8 * c + 4], vb.x), 0.0f);
            float v5 = fmaxf(fmaf(kf, smallf[8 * c + 5], vb.y), 0.0f);
            float v6 = fmaxf(fmaf(kf, smallf[8 * c + 6], vb.z), 0.0f);
            float v7 = fmaxf(fmaf(kf, smallf[8 * c + 7], vb.w), 0.0f);
            uint4 w = make_uint4(packh2(v0, v1), packh2(v2, v3),
                                 packh2(v4, v5), packh2(v6, v7));
            uint32_t off = row * 128 + ((c ^ (row & 7)) << 4);
            *(uint4*)(sm8 + SM_A + off) = w;
        }
    }
    __syncthreads();

    // B-fragment ldmatrix address: n16 x k16 pair-tile at (ntp, kt), base = blob offset
    //   lane group lg: n = ntp*16 + (lg&1)*8 + lr ; byte = kt*32 + (lg>>1)*16
    auto baddr = [&](uint32_t blob, int ntp, int kt) -> uint32_t {
        uint32_t n = ntp * 16 + ((lg & 1) << 3) + lr;
        uint32_t byte = kt * 32 + ((lg >> 1) << 4);
        return smb + blob + sw128(n * 128 + byte);
    };

    // ---- layer 2: C[128,64] = Ah @ (W2h + W2l), 2 products ----
    float acc2[2][8][4];
    #pragma unroll
    for (int mt = 0; mt < 2; mt++)
        #pragma unroll
        for (int nt = 0; nt < 8; nt++)
            #pragma unroll
            for (int e = 0; e < 4; e++) acc2[mt][nt][e] = 0.0f;

    #pragma unroll
    for (int kt = 0; kt < 4; kt++) {
        uint32_t ah[2][4];
        #pragma unroll
        for (int mt = 0; mt < 2; mt++) {
            int r = rbase + mt * 16 + (lane & 15);
            uint32_t cb = kt * 32 + ((lane >> 4) << 4);
            uint32_t off = r * 128 + (cb ^ ((r & 7) << 4));
            ldmatrix4(ah[mt][0], ah[mt][1], ah[mt][2], ah[mt][3], smb + SM_A + off);
        }
        #pragma unroll
        for (int ntp = 0; ntp < 4; ntp++) {
            uint32_t h0, h1, h2, h3, l0, l1, l2, l3;
            ldmatrix4(h0, h1, h2, h3, baddr(0, ntp, kt));       // W2 hi
            ldmatrix4(l0, l1, l2, l3, baddr(8192, ntp, kt));    // W2 lo
            #pragma unroll
            for (int mt = 0; mt < 2; mt++) {
                float* d0 = acc2[mt][2 * ntp];
                float* d1 = acc2[mt][2 * ntp + 1];
                mma16816(d0[0], d0[1], d0[2], d0[3], ah[mt][0], ah[mt][1], ah[mt][2], ah[mt][3], h0, h2);
                mma16816(d0[0], d0[1], d0[2], d0[3], ah[mt][0], ah[mt][1], ah[mt][2], ah[mt][3], l0, l2);
                mma16816(d1[0], d1[1], d1[2], d1[3], ah[mt][0], ah[mt][1], ah[mt][2], ah[mt][3], h1, h3);
                mma16816(d1[0], d1[1], d1[2], d1[3], ah[mt][0], ah[mt][1], ah[mt][2], ah[mt][3], l1, l3);
            }
        }
    }
    __syncthreads();   // all A reads done before overwrite

    // ---- epilogue L2: h2 = relu(C + b2) -> fp16 -> smem A ----
    #pragma unroll
    for (int mt = 0; mt < 2; mt++) {
        int r0 = rbase + mt * 16 + qr;
        #pragma unroll
        for (int nt = 0; nt < 8; nt++) {
            int cn = nt * 8 + 2 * q;
            float bb0 = smallf[64 + cn], bb1 = smallf[64 + cn + 1];
            float v0 = fmaxf(acc2[mt][nt][0] + bb0, 0.0f);
            float v1 = fmaxf(acc2[mt][nt][1] + bb1, 0.0f);
            float v2 = fmaxf(acc2[mt][nt][2] + bb0, 0.0f);
            float v3 = fmaxf(acc2[mt][nt][3] + bb1, 0.0f);
            uint32_t oa = sw128((uint32_t)(r0 * 128 + cn * 2));
            uint32_t ob = sw128((uint32_t)((r0 + 8) * 128 + cn * 2));
            *(uint32_t*)(sm8 + SM_A + oa) = packh2(v0, v1);
            *(uint32_t*)(sm8 + SM_A + ob) = packh2(v2, v3);
        }
    }
    __syncthreads();

    // ---- layer 3: C[128,32] = Ah @ (W3h + W3l) ----
    float acc3[2][4][4];
    #pragma unroll
    for (int mt = 0; mt < 2; mt++)
        #pragma unroll
        for (int nt = 0; nt < 4; nt++)
            #pragma unroll
            for (int e = 0; e < 4; e++) acc3[mt][nt][e] = 0.0f;

    #pragma unroll
    for (int kt = 0; kt < 4; kt++) {
        uint32_t ah[2][4];
        #pragma unroll
        for (int mt = 0; mt < 2; mt++) {
            int r = rbase + mt * 16 + (lane & 15);
            uint32_t cb = kt * 32 + ((lane >> 4) << 4);
            uint32_t off = r * 128 + (cb ^ ((r & 7) << 4));
            ldmatrix4(ah[mt][0], ah[mt][1], ah[mt][2], ah[mt][3], smb + SM_A + off);
        }
        #pragma unroll
        for (int ntp = 0; ntp < 2; ntp++) {
            uint32_t h0, h1, h2, h3, l0, l1, l2, l3;
            ldmatrix4(h0, h1, h2, h3, baddr(16384, ntp, kt));   // W3 hi
            ldmatrix4(l0, l1, l2, l3, baddr(20480, ntp, kt));   // W3 lo
            #pragma unroll
            for (int mt = 0; mt < 2; mt++) {
                float* d0 = acc3[mt][2 * ntp];
                float* d1 = acc3[mt][2 * ntp + 1];
                mma16816(d0[0], d0[1], d0[2], d0[3], ah[mt][0], ah[mt][1], ah[mt][2], ah[mt][3], h0, h2);
                mma16816(d0[0], d0[1], d0[2], d0[3], ah[mt][0], ah[mt][1], ah[mt][2], ah[mt][3], l0, l2);
                mma16816(d1[0], d1[1], d1[2], d1[3], ah[mt][0], ah[mt][1], ah[mt][2], ah[mt][3], h1, h3);
                mma16816(d1[0], d1[1], d1[2], d1[3], ah[mt][0], ah[mt][1], ah[mt][2], ah[mt][3], l1, l3);
            }
        }
    }

    // ---- epilogue L3: relu(C + b3) . W4, quad reduce, write ----
    #pragma unroll
    for (int mt = 0; mt < 2; mt++) {
        float sa = 0.0f, sb = 0.0f;
        #pragma unroll
        for (int nt = 0; nt < 4; nt++) {
            int cn = nt * 8 + 2 * q;
            float b0 = smallf[128 + cn], b1 = smallf[128 + cn + 1];
            float w0 = smallf[160 + cn], w1 = smallf[160 + cn + 1];
            sa = fmaf(fmaxf(acc3[mt][nt][0] + b0, 0.0f), w0, sa);
            sa = fmaf(fmaxf(acc3[mt][nt][1] + b1, 0.0f), w1, sa);
            sb = fmaf(fmaxf(acc3[mt][nt][2] + b0, 0.0f), w0, sb);
            sb = fmaf(fmaxf(acc3[mt][nt][3] + b1, 0.0f), w1, sb);
        }
        sa += __shfl_xor_sync(0xFFFFFFFFu, sa, 1);
        sa += __shfl_xor_sync(0xFFFFFFFFu, sa, 2);
        sb += __shfl_xor_sync(0xFFFFFFFFu, sb, 1);
        sb += __shfl_xor_sync(0xFFFFFFFFu, sb, 2);
        if (q == 0) {
            int ra = blockIdx.x * 128 + rbase + mt * 16 + qr;
            float b4v = smallf[192];
            if (ra < T)     out[ra]     = sa + b4v;
            if (ra + 8 < T) out[ra + 8] = sb + b4v;
        }
    }
}

// ================= launcher =================
extern "C" void kernel_launch(void* const* d_in, const int* in_sizes, int n_in,
                              void* d_out, int out_size) {
    const float* x          = (const float*)d_in[0];
    const float* h_dag      = (const float*)d_in[1];
    const float* h_glob     = (const float*)d_in[2];
    const int* ptr          = (const int*)d_in[3];
    const int* job_idx      = (const int*)d_in[4];
    const int* num_exec     = (const int*)d_in[5];
    const int* exec_aidx    = (const int*)d_in[6];
    const float* W1 = (const float*)d_in[7];
    const float* b1 = (const float*)d_in[8];
    const float* W2 = (const float*)d_in[9];
    const float* b2 = (const float*)d_in[10];
    const float* W3 = (const float*)d_in[11];
    const float* b3 = (const float*)d_in[12];
    const float* W4 = (const float*)d_in[13];
    const float* b4 = (const float*)d_in[14];
    float* out = (float*)d_out;

    int J = in_sizes[4];
    int T = in_sizes[6];

    cudaFuncSetAttribute(k_mlp_mma, cudaFuncAttributeMaxDynamicSharedMemorySize, KM_SMEM);

    int nblocks256 = (J + 255) / 256;

    k_p1<<<nblocks256, 256>>>(job_idx, num_exec, J);
    k_scan<<<1, 512>>>(nblocks256);
    k_p3<<<nblocks256, 256>>>(J);
    k_base1<<<(J + 63) / 64, 256>>>(x, h_dag, h_glob, ptr, job_idx, W1, b1, J);
    k_wprep<<<25, 256>>>(W1, W2, b2, W3, b3, W4, b4);
    k_mlp_mma<<<(T + 127) / 128, 128, KM_SMEM>>>(exec_aidx, out, T);
}

// round 9
// speedup vs baseline: 1.0378x; 1.0378x over previous
#include <cuda_runtime.h>
#include <cuda_fp16.h>
#include <stdint.h>

// ---------------- problem constants ----------------
#define NUM_EXEC   50
#define MAXB       60000
#define MAXT       (MAXB * NUM_EXEC)

typedef unsigned long long ull;

// ---------------- device scratch ----------------
__device__ int   g_nsel[MAXB];
__device__ int   g_blocksum[512];
__device__ int   g_rowjob[MAXT];
__device__ float g_base1[(size_t)MAXB * 64];
// prepped weight blob (exact smem image):
//  [0,8192)      W2^T hi  fp16 [n=64][k=64], 128B rows, XOR-16B swizzle
//  [8192,16384)  W2^T lo  (fp16 residual)
//  [16384,20480) W3^T hi  [n=32][k=64]
//  [20480,24576) W3^T lo
//  [24576,25600) fp32 smalls: W1L[64] b2[64] b3[32] W4[32] b4[1]
__device__ __align__(16) unsigned char g_wblob[25600];

// ---------------- helpers ----------------
__device__ __forceinline__ ull fma2(ull a, ull b, ull c) {
    ull d;
    asm("fma.rn.f32x2 %0, %1, %2, %3;" : "=l"(d) : "l"(a), "l"(b), "l"(c));
    return d;
}
__device__ __forceinline__ ull pack2(float a, float b) {
    ull r;
    asm("mov.b64 %0, {%1,%2};" : "=l"(r) : "f"(a), "f"(b));
    return r;
}
__device__ __forceinline__ void unpack2(ull v, float& a, float& b) {
    asm("mov.b64 {%0,%1}, %2;" : "=f"(a), "=f"(b) : "l"(v));
}
__device__ __forceinline__ uint32_t smem_u32(const void* p) {
    uint32_t a;
    asm("{ .reg .u64 t; cvta.to.shared.u64 t, %1; cvt.u32.u64 %0, t; }" : "=r"(a) : "l"(p));
    return a;
}
// pack (lo_elem, hi_elem) -> f16x2, lo_elem in low 16 bits
__device__ __forceinline__ uint32_t packh2(float lov, float hiv) {
    uint32_t r;
    asm("cvt.rn.f16x2.f32 %0, %1, %2;" : "=r"(r) : "f"(hiv), "f"(lov));
    return r;
}
__device__ __forceinline__ void ldmatrix4(uint32_t& a0, uint32_t& a1, uint32_t& a2,
                                          uint32_t& a3, uint32_t addr) {
    asm volatile("ldmatrix.sync.aligned.m8n8.x4.shared.b16 {%0,%1,%2,%3}, [%4];"
                 : "=r"(a0), "=r"(a1), "=r"(a2), "=r"(a3) : "r"(addr));
}
__device__ __forceinline__ void mma16816(float& d0, float& d1, float& d2, float& d3,
                                         uint32_t a0, uint32_t a1, uint32_t a2, uint32_t a3,
                                         uint32_t b0, uint32_t b1) {
    asm volatile("mma.sync.aligned.m16n8k16.row.col.f32.f16.f16.f32 "
                 "{%0,%1,%2,%3}, {%4,%5,%6,%7}, {%8,%9}, {%0,%1,%2,%3};"
                 : "+f"(d0), "+f"(d1), "+f"(d2), "+f"(d3)
                 : "r"(a0), "r"(a1), "r"(a2), "r"(a3), "r"(b0), "r"(b1));
}
// XOR-16B swizzle for 128B rows
__device__ __host__ __forceinline__ uint32_t sw128(uint32_t b) {
    return b ^ ((b >> 3) & 0x70);
}

// ================= prologue 1: nsel gather + per-256 block sums =================
__global__ void k_p1(const int* __restrict__ job_indices,
                     const int* __restrict__ num_exec_acts, int J) {
    __shared__ int s[256];
    int j = blockIdx.x * 256 + threadIdx.x;
    int v = 0;
    if (j < J) { v = num_exec_acts[job_indices[j]]; g_nsel[j] = v; }
    s[threadIdx.x] = v;
    __syncthreads();
    #pragma unroll
    for (int o = 128; o > 0; o >>= 1) {
        if (threadIdx.x < o) s[threadIdx.x] += s[threadIdx.x + o];
        __syncthreads();
    }
    if (threadIdx.x == 0) g_blocksum[blockIdx.x] = s[0];
}

// ================= prologue 2: exclusive scan of block sums =================
__global__ void k_scan(int nblocks) {
    __shared__ int s[512];
    int tid = threadIdx.x;
    int v = (tid < nblocks) ? g_blocksum[tid] : 0;
    s[tid] = v;
    __syncthreads();
    for (int o = 1; o < 512; o <<= 1) {
        int t = (tid >= o) ? s[tid - o] : 0;
        __syncthreads();
        s[tid] += t;
        __syncthreads();
    }
    if (tid < nblocks) g_blocksum[tid] = s[tid] - v;
}

// ================= prologue 3: per-job start + row->job fill =================
__global__ void k_p3(int J) {
    __shared__ int s[256];
    int tid = threadIdx.x;
    int j = blockIdx.x * 256 + tid;
    int v = (j < J) ? g_nsel[j] : 0;
    s[tid] = v;
    __syncthreads();
    for (int o = 1; o < 256; o <<= 1) {
        int t = (tid >= o) ? s[tid - o] : 0;
        __syncthreads();
        s[tid] += t;
        __syncthreads();
    }
    if (j < J) {
        int start = (s[tid] - v) + g_blocksum[blockIdx.x];
        for (int k = 0; k < v; k++) g_rowjob[start + k] = j;
    }
}

// ================= prologue 4: base1 — 64 jobs/block, 2 jobs + 2 acc chains ==========
__global__ void __launch_bounds__(256) k_base1(
    const float* __restrict__ x, const float* __restrict__ h_dag,
    const float* __restrict__ h_glob,
    const int* __restrict__ ptr, const int* __restrict__ jidx,
    const float* __restrict__ W1, const float* __restrict__ b1, int J) {
    __shared__ __align__(16) float sW1[35 * 64];
    __shared__ __align__(16) float sB1[64];
    for (int i = threadIdx.x; i < 35 * 64; i += blockDim.x) sW1[i] = W1[i];
    for (int i = threadIdx.x; i < 64; i += blockDim.x)      sB1[i] = b1[i];
    __syncthreads();

    const int warp = threadIdx.x >> 5;
    const int lane = threadIdx.x & 31;
    const int jbase = blockIdx.x * 64 + warp;

    #pragma unroll 1
    for (int it = 0; it < 4; it++) {
        int j0 = jbase + it * 16;
        if (j0 >= J) break;
        int j1 = j0 + 8;
        bool has1 = (j1 < J);
        int j1c = has1 ? j1 : j0;

        int ji0 = jidx[j0], ji1 = jidx[j1c];
        const float* xr0 = x + (long long)ptr[ji0] * 5;
        const float* xr1 = x + (long long)ptr[ji1] * 5;
        const float* hd0 = h_dag + (long long)ji0 * 16;
        const float* hd1 = h_dag + (long long)ji1 * 16;
        const float* hg0 = h_glob + (long long)j0 * 16;
        const float* hg1 = h_glob + (long long)j1c * 16;

        ull bias = pack2(sB1[2 * lane], sB1[2 * lane + 1]);
        ull zero = pack2(0.0f, 0.0f);
        ull a0A = bias, a0B = zero;     // job0, two chains
        ull a1A = bias, a1B = zero;     // job1, two chains

        // x features (3): chain A
        #pragma unroll
        for (int i = 0; i < 3; i++) {
            ull w = *(const ull*)&sW1[i * 64 + 2 * lane];
            float v0 = xr0[i], v1 = xr1[i];
            a0A = fma2(pack2(v0, v0), w, a0A);
            a1A = fma2(pack2(v1, v1), w, a1A);
        }
        // h_dag (16): alternate chains
        #pragma unroll
        for (int i = 0; i < 16; i++) {
            ull w = *(const ull*)&sW1[(3 + i) * 64 + 2 * lane];
            float v0 = hd0[i], v1 = hd1[i];
            if (i & 1) { a0B = fma2(pack2(v0, v0), w, a0B); a1B = fma2(pack2(v1, v1), w, a1B); }
            else       { a0A = fma2(pack2(v0, v0), w, a0A); a1A = fma2(pack2(v1, v1), w, a1A); }
        }
        // h_glob (16): alternate chains
        #pragma unroll
        for (int i = 0; i < 16; i++) {
            ull w = *(const ull*)&sW1[(19 + i) * 64 + 2 * lane];
            float v0 = hg0[i], v1 = hg1[i];
            if (i & 1) { a0B = fma2(pack2(v0, v0), w, a0B); a1B = fma2(pack2(v1, v1), w, a1B); }
            else       { a0A = fma2(pack2(v0, v0), w, a0A); a1A = fma2(pack2(v1, v1), w, a1A); }
        }

        float xa, xb, ya, yb;
        unpack2(a0A, xa, xb);
        unpack2(a0B, ya, yb);
        float* d0 = g_base1 + (size_t)j0 * 64 + 2 * lane;
        d0[0] = xa + ya;
        d0[1] = xb + yb;
        if (has1) {
            unpack2(a1A, xa, xb);
            unpack2(a1B, ya, yb);
            float* d1 = g_base1 + (size_t)j1 * 64 + 2 * lane;
            d1[0] = xa + ya;
            d1[1] = xb + yb;
        }
    }
}

// ================= prologue 5: weight prep (transpose + fp16 split + swizzle) =====
__global__ void k_wprep(const float* __restrict__ W1, const float* __restrict__ W2,
                        const float* __restrict__ b2, const float* __restrict__ W3,
                        const float* __restrict__ b3, const float* __restrict__ W4,
                        const float* __restrict__ b4) {
    int tid = blockIdx.x * blockDim.x + threadIdx.x;
    if (tid < 4096) {                 // W2^T: [n][k] = W2[k][n]
        int n = tid >> 6, k = tid & 63;
        float w = W2[k * 64 + n];
        __half h = __float2half_rn(w);
        __half l = __float2half_rn(w - __half2float(h));
        uint32_t sw = sw128((uint32_t)(n * 128 + 2 * k));
        *(__half*)(g_wblob + sw)        = h;
        *(__half*)(g_wblob + 8192 + sw) = l;
    } else if (tid < 6144) {          // W3^T: [n][k] = W3[k][n]
        int e = tid - 4096;
        int n = e >> 6, k = e & 63;
        float w = W3[k * 32 + n];
        __half h = __float2half_rn(w);
        __half l = __float2half_rn(w - __half2float(h));
        uint32_t sw = sw128((uint32_t)(n * 128 + 2 * k));
        *(__half*)(g_wblob + 16384 + sw) = h;
        *(__half*)(g_wblob + 20480 + sw) = l;
    } else if (tid < 6144 + 256) {
        int i = tid - 6144;
        float* s = (float*)(g_wblob + 24576);
        if (i < 64)       s[i] = W1[35 * 64 + i];
        else if (i < 128) s[i] = b2[i - 64];
        else if (i < 160) s[i] = b3[i - 128];
        else if (i < 192) s[i] = W4[i - 160];
        else if (i == 192) s[192] = b4[0];
    }
}

// ================= main: mma.sync (fp16 2-product) fused MLP, 128 rows/CTA ==========
// (exact R7 configuration — scalar B loads)
// dyn smem: [0,25600) weight blob image; [25600,41984) A fp16 [128][128B] swizzled
#define SM_A    25600
#define KM_SMEM 41984

__global__ void __launch_bounds__(128, 4) k_mlp_mma(
    const int* __restrict__ exec_act_idx, float* __restrict__ out, int T) {

    extern __shared__ unsigned char sm8[];
    const uint32_t smb = smem_u32(sm8);
    const float* smallf = (const float*)(sm8 + 24576);

    const int tid  = threadIdx.x;
    const int warp = tid >> 5;
    const int lane = tid & 31;
    const int q    = lane & 3;        // quad index
    const int qr   = lane >> 2;       // row-within-8
    const int rbase = warp * 32;

    // ---- copy prepped weights + smalls (25600 B) ----
    {
        const uint4* src = (const uint4*)g_wblob;
        uint4* dst = (uint4*)sm8;
        #pragma unroll
        for (int it = 0; it < 13; it++) {
            int i = tid + it * 128;
            if (i < 1600) dst[i] = src[i];
        }
    }
    __syncthreads();

    const int t  = blockIdx.x * 128 + tid;
    const int tt = (t < T) ? t : (T - 1);

    // ---- layer 1: h1 = relu(base1[j] + kf*W1L) -> fp16 -> smem A ----
    {
        int j   = g_rowjob[tt];
        float kf = (float)exec_act_idx[tt] * (1.0f / (float)NUM_EXEC);
        const float4* bp = (const float4*)(g_base1 + (size_t)j * 64);
        const int row = tid;
        #pragma unroll
        for (int c = 0; c < 8; c++) {               // 8 chunks x 8 values = 64
            float4 va = bp[2 * c];
            float4 vb = bp[2 * c + 1];
            float v0 = fmaxf(fmaf(kf, smallf[8 * c + 0], va.x), 0.0f);
            float v1 = fmaxf(fmaf(kf, smallf[8 * c + 1], va.y), 0.0f);
            float v2 = fmaxf(fmaf(kf, smallf[8 * c + 2], va.z), 0.0f);
            float v3 = fmaxf(fmaf(kf, smallf[8 * c + 3], va.w), 0.0f);
            float v4 = fmaxf(fmaf(kf, smallf[8 * c + 4], vb.x), 0.0f);
            float v5 = fmaxf(fmaf(kf, smallf[8 * c + 5], vb.y), 0.0f);
            float v6 = fmaxf(fmaf(kf, smallf[8 * c + 6], vb.z), 0.0f);
            float v7 = fmaxf(fmaf(kf, smallf[8 * c + 7], vb.w), 0.0f);
            uint4 w = make_uint4(packh2(v0, v1), packh2(v2, v3),
                                 packh2(v4, v5), packh2(v6, v7));
            uint32_t off = row * 128 + ((c ^ (row & 7)) << 4);
            *(uint4*)(sm8 + SM_A + off) = w;
        }
    }
    __syncthreads();

    // ---- layer 2: C[128,64] = Ah @ (W2h + W2l), 2 products ----
    float acc2[2][8][4];
    #pragma unroll
    for (int mt = 0; mt < 2; mt++)
        #pragma unroll
        for (int nt = 0; nt < 8; nt++)
            #pragma unroll
            for (int e = 0; e < 4; e++) acc2[mt][nt][e] = 0.0f;

    #pragma unroll
    for (int kt = 0; kt < 4; kt++) {
        uint32_t ah[2][4];
        #pragma unroll
        for (int mt = 0; mt < 2; mt++) {
            int r = rbase + mt * 16 + (lane & 15);
            uint32_t cb = kt * 32 + ((lane >> 4) << 4);
            uint32_t off = r * 128 + (cb ^ ((r & 7) << 4));
            ldmatrix4(ah[mt][0], ah[mt][1], ah[mt][2], ah[mt][3], smb + SM_A + off);
        }
        #pragma unroll
        for (int nt = 0; nt < 8; nt++) {
            int n = nt * 8 + qr;
            uint32_t byte0 = n * 128 + kt * 32 + 4 * q;
            uint32_t o0 = sw128(byte0), o1 = sw128(byte0 + 16);
            uint32_t bh0 = *(const uint32_t*)(sm8 + o0);
            uint32_t bh1 = *(const uint32_t*)(sm8 + o1);
            uint32_t bl0 = *(const uint32_t*)(sm8 + 8192 + o0);
            uint32_t bl1 = *(const uint32_t*)(sm8 + 8192 + o1);
            #pragma unroll
            for (int mt = 0; mt < 2; mt++) {
                float* d = acc2[mt][nt];
                mma16816(d[0], d[1], d[2], d[3], ah[mt][0], ah[mt][1], ah[mt][2], ah[mt][3], bh0, bh1);
                mma16816(d[0], d[1], d[2], d[3], ah[mt][0], ah[mt][1], ah[mt][2], ah[mt][3], bl0, bl1);
            }
        }
    }
    __syncthreads();   // all A reads done before overwrite

    // ---- epilogue L2: h2 = relu(C + b2) -> fp16 -> smem A ----
    #pragma unroll
    for (int mt = 0; mt < 2; mt++) {
        int r0 = rbase + mt * 16 + qr;
        #pragma unroll
        for (int nt = 0; nt < 8; nt++) {
            int cn = nt * 8 + 2 * q;
            float bb0 = smallf[64 + cn], bb1 = smallf[64 + cn + 1];
            float v0 = fmaxf(acc2[mt][nt][0] + bb0, 0.0f);
            float v1 = fmaxf(acc2[mt][nt][1] + bb1, 0.0f);
            float v2 = fmaxf(acc2[mt][nt][2] + bb0, 0.0f);
            float v3 = fmaxf(acc2[mt][nt][3] + bb1, 0.0f);
            uint32_t oa = sw128((uint32_t)(r0 * 128 + cn * 2));
            uint32_t ob = sw128((uint32_t)((r0 + 8) * 128 + cn * 2));
            *(uint32_t*)(sm8 + SM_A + oa) = packh2(v0, v1);
            *(uint32_t*)(sm8 + SM_A + ob) = packh2(v2, v3);
        }
    }
    __syncthreads();

    // ---- layer 3: C[128,32] = Ah @ (W3h + W3l) ----
    float acc3[2][4][4];
    #pragma unroll
    for (int mt = 0; mt < 2; mt++)
        #pragma unroll
        for (int nt = 0; nt < 4; nt++)
            #pragma unroll
            for (int e = 0; e < 4; e++) acc3[mt][nt][e] = 0.0f;

    #pragma unroll
    for (int kt = 0; kt < 4; kt++) {
        uint32_t ah[2][4];
        #pragma unroll
        for (int mt = 0; mt < 2; mt++) {
            int r = rbase + mt * 16 + (lane & 15);
            uint32_t cb = kt * 32 + ((lane >> 4) << 4);
            uint32_t off = r * 128 + (cb ^ ((r & 7) << 4));
            ldmatrix4(ah[mt][0], ah[mt][1], ah[mt][2], ah[mt][3], smb + SM_A + off);
        }
        #pragma unroll
        for (int nt = 0; nt < 4; nt++) {
            int n = nt * 8 + qr;
            uint32_t byte0 = n * 128 + kt * 32 + 4 * q;
            uint32_t o0 = sw128(byte0), o1 = sw128(byte0 + 16);
            uint32_t bh0 = *(const uint32_t*)(sm8 + 16384 + o0);
            uint32_t bh1 = *(const uint32_t*)(sm8 + 16384 + o1);
            uint32_t bl0 = *(const uint32_t*)(sm8 + 20480 + o0);
            uint32_t bl1 = *(const uint32_t*)(sm8 + 20480 + o1);
            #pragma unroll
            for (int mt = 0; mt < 2; mt++) {
                float* d = acc3[mt][nt];
                mma16816(d[0], d[1], d[2], d[3], ah[mt][0], ah[mt][1], ah[mt][2], ah[mt][3], bh0, bh1);
                mma16816(d[0], d[1], d[2], d[3], ah[mt][0], ah[mt][1], ah[mt][2], ah[mt][3], bl0, bl1);
            }
        }
    }

    // ---- epilogue L3: relu(C + b3) . W4, quad reduce, write ----
    #pragma unroll
    for (int mt = 0; mt < 2; mt++) {
        float sa = 0.0f, sb = 0.0f;
        #pragma unroll
        for (int nt = 0; nt < 4; nt++) {
            int cn = nt * 8 + 2 * q;
            float b0 = smallf[128 + cn], b1 = smallf[128 + cn + 1];
            float w0 = smallf[160 + cn], w1 = smallf[160 + cn + 1];
            sa = fmaf(fmaxf(acc3[mt][nt][0] + b0, 0.0f), w0, sa);
            sa = fmaf(fmaxf(acc3[mt][nt][1] + b1, 0.0f), w1, sa);
            sb = fmaf(fmaxf(acc3[mt][nt][2] + b0, 0.0f), w0, sb);
            sb = fmaf(fmaxf(acc3[mt][nt][3] + b1, 0.0f), w1, sb);
        }
        sa += __shfl_xor_sync(0xFFFFFFFFu, sa, 1);
        sa += __shfl_xor_sync(0xFFFFFFFFu, sa, 2);
        sb += __shfl_xor_sync(0xFFFFFFFFu, sb, 1);
        sb += __shfl_xor_sync(0xFFFFFFFFu, sb, 2);
        if (q == 0) {
            int ra = blockIdx.x * 128 + rbase + mt * 16 + qr;
            float b4v = smallf[192];
            if (ra < T)     out[ra]     = sa + b4v;
            if (ra + 8 < T) out[ra + 8] = sb + b4v;
        }
    }
}

// ================= launcher =================
extern "C" void kernel_launch(void* const* d_in, const int* in_sizes, int n_in,
                              void* d_out, int out_size) {
    const float* x          = (const float*)d_in[0];
    const float* h_dag      = (const float*)d_in[1];
    const float* h_glob     = (const float*)d_in[2];
    const int* ptr          = (const int*)d_in[3];
    const int* job_idx      = (const int*)d_in[4];
    const int* num_exec     = (const int*)d_in[5];
    const int* exec_aidx    = (const int*)d_in[6];
    const float* W1 = (const float*)d_in[7];
    const float* b1 = (const float*)d_in[8];
    const float* W2 = (const float*)d_in[9];
    const float* b2 = (const float*)d_in[10];
    const float* W3 = (const float*)d_in[11];
    const float* b3 = (const float*)d_in[12];
    const float* W4 = (const float*)d_in[13];
    const float* b4 = (const float*)d_in[14];
    float* out = (float*)d_out;

    int J = in_sizes[4];
    int T = in_sizes[6];

    cudaFuncSetAttribute(k_mlp_mma, cudaFuncAttributeMaxDynamicSharedMemorySize, KM_SMEM);

    int nblocks256 = (J + 255) / 256;

    k_p1<<<nblocks256, 256>>>(job_idx, num_exec, J);
    k_scan<<<1, 512>>>(nblocks256);
    k_p3<<<nblocks256, 256>>>(J);
    k_base1<<<(J + 63) / 64, 256>>>(x, h_dag, h_glob, ptr, job_idx, W1, b1, J);
    k_wprep<<<25, 256>>>(W1, W2, b2, W3, b3, W4, b4);
    k_mlp_mma<<<(T + 127) / 128, 128, KM_SMEM>>>(exec_aidx, out, T);
}

// round 10
// speedup vs baseline: 1.0729x; 1.0337x over previous
#include <cuda_runtime.h>
#include <cuda_fp16.h>
#include <stdint.h>

// ---------------- problem constants ----------------
#define NUM_EXEC   50
#define MAXB       60000
#define MAXT       (MAXB * NUM_EXEC)

typedef unsigned long long ull;

// ---------------- device scratch ----------------
__device__ int   g_nsel[MAXB];
__device__ int   g_blocksum[512];
__device__ int   g_rowjob[MAXT];
__device__ float g_base1[(size_t)MAXB * 64];
// prepped weight blob (exact smem image), FRAGMENT-ORDERED B:
//  [0,16384)     W2 frags: for kt(4) x nt(8) x lane(32): uint4 {bh0,bh1,bl0,bl1}
//  [16384,24576) W3 frags: for kt(4) x nt(4) x lane(32): uint4
//  [24576,25600) fp32 smalls: W1L[64] b2[64] b3[32] W4[32] b4[1]
__device__ __align__(16) unsigned char g_wblob[25600];

// ---------------- helpers ----------------
__device__ __forceinline__ ull fma2(ull a, ull b, ull c) {
    ull d;
    asm("fma.rn.f32x2 %0, %1, %2, %3;" : "=l"(d) : "l"(a), "l"(b), "l"(c));
    return d;
}
__device__ __forceinline__ ull pack2(float a, float b) {
    ull r;
    asm("mov.b64 %0, {%1,%2};" : "=l"(r) : "f"(a), "f"(b));
    return r;
}
__device__ __forceinline__ void unpack2(ull v, float& a, float& b) {
    asm("mov.b64 {%0,%1}, %2;" : "=f"(a), "=f"(b) : "l"(v));
}
__device__ __forceinline__ uint32_t smem_u32(const void* p) {
    uint32_t a;
    asm("{ .reg .u64 t; cvta.to.shared.u64 t, %1; cvt.u32.u64 %0, t; }" : "=r"(a) : "l"(p));
    return a;
}
// pack (lo_elem, hi_elem) -> f16x2, lo_elem in low 16 bits
__device__ __forceinline__ uint32_t packh2(float lov, float hiv) {
    uint32_t r;
    asm("cvt.rn.f16x2.f32 %0, %1, %2;" : "=r"(r) : "f"(hiv), "f"(lov));
    return r;
}
__device__ __forceinline__ void ldmatrix4(uint32_t& a0, uint32_t& a1, uint32_t& a2,
                                          uint32_t& a3, uint32_t addr) {
    asm volatile("ldmatrix.sync.aligned.m8n8.x4.shared.b16 {%0,%1,%2,%3}, [%4];"
                 : "=r"(a0), "=r"(a1), "=r"(a2), "=r"(a3) : "r"(addr));
}
__device__ __forceinline__ void mma16816(float& d0, float& d1, float& d2, float& d3,
                                         uint32_t a0, uint32_t a1, uint32_t a2, uint32_t a3,
                                         uint32_t b0, uint32_t b1) {
    asm volatile("mma.sync.aligned.m16n8k16.row.col.f32.f16.f16.f32 "
                 "{%0,%1,%2,%3}, {%4,%5,%6,%7}, {%8,%9}, {%0,%1,%2,%3};"
                 : "+f"(d0), "+f"(d1), "+f"(d2), "+f"(d3)
                 : "r"(a0), "r"(a1), "r"(a2), "r"(a3), "r"(b0), "r"(b1));
}
// XOR-16B swizzle for 128B rows (A tile only)
__device__ __host__ __forceinline__ uint32_t sw128(uint32_t b) {
    return b ^ ((b >> 3) & 0x70);
}

// ================= prologue 1: nsel gather + per-256 block sums =================
__global__ void k_p1(const int* __restrict__ job_indices,
                     const int* __restrict__ num_exec_acts, int J) {
    __shared__ int s[256];
    int j = blockIdx.x * 256 + threadIdx.x;
    int v = 0;
    if (j < J) { v = num_exec_acts[job_indices[j]]; g_nsel[j] = v; }
    s[threadIdx.x] = v;
    __syncthreads();
    #pragma unroll
    for (int o = 128; o > 0; o >>= 1) {
        if (threadIdx.x < o) s[threadIdx.x] += s[threadIdx.x + o];
        __syncthreads();
    }
    if (threadIdx.x == 0) g_blocksum[blockIdx.x] = s[0];
}

// ================= prologue 2: exclusive scan of block sums =================
__global__ void k_scan(int nblocks) {
    __shared__ int s[512];
    int tid = threadIdx.x;
    int v = (tid < nblocks) ? g_blocksum[tid] : 0;
    s[tid] = v;
    __syncthreads();
    for (int o = 1; o < 512; o <<= 1) {
        int t = (tid >= o) ? s[tid - o] : 0;
        __syncthreads();
        s[tid] += t;
        __syncthreads();
    }
    if (tid < nblocks) g_blocksum[tid] = s[tid] - v;
}

// ================= prologue 3: per-job start + row->job fill =================
__global__ void k_p3(int J) {
    __shared__ int s[256];
    int tid = threadIdx.x;
    int j = blockIdx.x * 256 + tid;
    int v = (j < J) ? g_nsel[j] : 0;
    s[tid] = v;
    __syncthreads();
    for (int o = 1; o < 256; o <<= 1) {
        int t = (tid >= o) ? s[tid - o] : 0;
        __syncthreads();
        s[tid] += t;
        __syncthreads();
    }
    if (j < J) {
        int start = (s[tid] - v) + g_blocksum[blockIdx.x];
        for (int k = 0; k < v; k++) g_rowjob[start + k] = j;
    }
}

// ================= prologue 4: base1 — 64 jobs/block, 2 jobs + 2 acc chains ==========
__global__ void __launch_bounds__(256) k_base1(
    const float* __restrict__ x, const float* __restrict__ h_dag,
    const float* __restrict__ h_glob,
    const int* __restrict__ ptr, const int* __restrict__ jidx,
    const float* __restrict__ W1, const float* __restrict__ b1, int J) {
    __shared__ __align__(16) float sW1[35 * 64];
    __shared__ __align__(16) float sB1[64];
    for (int i = threadIdx.x; i < 35 * 64; i += blockDim.x) sW1[i] = W1[i];
    for (int i = threadIdx.x; i < 64; i += blockDim.x)      sB1[i] = b1[i];
    __syncthreads();

    const int warp = threadIdx.x >> 5;
    const int lane = threadIdx.x & 31;
    const int jbase = blockIdx.x * 64 + warp;

    #pragma unroll 1
    for (int it = 0; it < 4; it++) {
        int j0 = jbase + it * 16;
        if (j0 >= J) break;
        int j1 = j0 + 8;
        bool has1 = (j1 < J);
        int j1c = has1 ? j1 : j0;

        int ji0 = jidx[j0], ji1 = jidx[j1c];
        const float* xr0 = x + (long long)ptr[ji0] * 5;
        const float* xr1 = x + (long long)ptr[ji1] * 5;
        const float* hd0 = h_dag + (long long)ji0 * 16;
        const float* hd1 = h_dag + (long long)ji1 * 16;
        const float* hg0 = h_glob + (long long)j0 * 16;
        const float* hg1 = h_glob + (long long)j1c * 16;

        ull bias = pack2(sB1[2 * lane], sB1[2 * lane + 1]);
        ull zero = pack2(0.0f, 0.0f);
        ull a0A = bias, a0B = zero;
        ull a1A = bias, a1B = zero;

        #pragma unroll
        for (int i = 0; i < 3; i++) {
            ull w = *(const ull*)&sW1[i * 64 + 2 * lane];
            float v0 = xr0[i], v1 = xr1[i];
            a0A = fma2(pack2(v0, v0), w, a0A);
            a1A = fma2(pack2(v1, v1), w, a1A);
        }
        #pragma unroll
        for (int i = 0; i < 16; i++) {
            ull w = *(const ull*)&sW1[(3 + i) * 64 + 2 * lane];
            float v0 = hd0[i], v1 = hd1[i];
            if (i & 1) { a0B = fma2(pack2(v0, v0), w, a0B); a1B = fma2(pack2(v1, v1), w, a1B); }
            else       { a0A = fma2(pack2(v0, v0), w, a0A); a1A = fma2(pack2(v1, v1), w, a1A); }
        }
        #pragma unroll
        for (int i = 0; i < 16; i++) {
            ull w = *(const ull*)&sW1[(19 + i) * 64 + 2 * lane];
            float v0 = hg0[i], v1 = hg1[i];
            if (i & 1) { a0B = fma2(pack2(v0, v0), w, a0B); a1B = fma2(pack2(v1, v1), w, a1B); }
            else       { a0A = fma2(pack2(v0, v0), w, a0A); a1A = fma2(pack2(v1, v1), w, a1A); }
        }

        float xa, xb, ya, yb;
        unpack2(a0A, xa, xb);
        unpack2(a0B, ya, yb);
        float* d0 = g_base1 + (size_t)j0 * 64 + 2 * lane;
        d0[0] = xa + ya;
        d0[1] = xb + yb;
        if (has1) {
            unpack2(a1A, xa, xb);
            unpack2(a1B, ya, yb);
            float* d1 = g_base1 + (size_t)j1 * 64 + 2 * lane;
            d1[0] = xa + ya;
            d1[1] = xb + yb;
        }
    }
}

// ================= prologue 5: weight prep — FRAGMENT-ORDERED fp16 split ==========
// Each (kt, nt, lane) thread emits uint4 {bh0, bh1, bl0, bl1}:
//   q = lane&3, qr = lane>>2, n = nt*8 + qr
//   k0 = kt*16 + 2q, k1 = k0+1, k2 = k0+8, k3 = k2+1
//   bh0 = f16x2(hi(W[k0][n]), hi(W[k1][n])), bh1 = f16x2(hi(k2), hi(k3)); bl* = residuals
__global__ void k_wprep(const float* __restrict__ W1, const float* __restrict__ W2,
                        const float* __restrict__ b2, const float* __restrict__ W3,
                        const float* __restrict__ b3, const float* __restrict__ W4,
                        const float* __restrict__ b4) {
    int tid = blockIdx.x * blockDim.x + threadIdx.x;
    if (tid < 1024) {                 // W2 fragments: kt(4) x nt(8) x lane(32)
        int kt = tid >> 8, nt = (tid >> 5) & 7, lane = tid & 31;
        int q = lane & 3, qr = lane >> 2;
        int n = nt * 8 + qr;
        int k0 = kt * 16 + 2 * q;
        float w0 = W2[(k0    ) * 64 + n], w1 = W2[(k0 + 1) * 64 + n];
        float w2 = W2[(k0 + 8) * 64 + n], w3 = W2[(k0 + 9) * 64 + n];
        float h0 = __half2float(__float2half_rn(w0));
        float h1 = __half2float(__float2half_rn(w1));
        float h2 = __half2float(__float2half_rn(w2));
        float h3 = __half2float(__float2half_rn(w3));
        uint4 v;
        v.x = packh2(h0, h1);
        v.y = packh2(h2, h3);
        v.z = packh2(w0 - h0, w1 - h1);
        v.w = packh2(w2 - h2, w3 - h3);
        ((uint4*)g_wblob)[tid] = v;
    } else if (tid < 1536) {          // W3 fragments: kt(4) x nt(4) x lane(32)
        int e = tid - 1024;
        int kt = e >> 7, nt = (e >> 5) & 3, lane = e & 31;
        int q = lane & 3, qr = lane >> 2;
        int n = nt * 8 + qr;
        int k0 = kt * 16 + 2 * q;
        float w0 = W3[(k0    ) * 32 + n], w1 = W3[(k0 + 1) * 32 + n];
        float w2 = W3[(k0 + 8) * 32 + n], w3 = W3[(k0 + 9) * 32 + n];
        float h0 = __half2float(__float2half_rn(w0));
        float h1 = __half2float(__float2half_rn(w1));
        float h2 = __half2float(__float2half_rn(w2));
        float h3 = __half2float(__float2half_rn(w3));
        uint4 v;
        v.x = packh2(h0, h1);
        v.y = packh2(h2, h3);
        v.z = packh2(w0 - h0, w1 - h1);
        v.w = packh2(w2 - h2, w3 - h3);
        ((uint4*)g_wblob)[1024 + e] = v;
    } else if (tid < 1536 + 256) {
        int i = tid - 1536;
        float* s = (float*)(g_wblob + 24576);
        if (i < 64)       s[i] = W1[35 * 64 + i];
        else if (i < 128) s[i] = b2[i - 64];
        else if (i < 160) s[i] = b3[i - 128];
        else if (i < 192) s[i] = W4[i - 160];
        else if (i == 192) s[192] = b4[0];
    }
}

// ================= main: mma.sync (fp16 2-product), frag-ordered B, 128 rows/CTA ====
// dyn smem: [0,25600) weight blob image; [25600,41984) A fp16 [128][128B] swizzled
#define SM_A    25600
#define KM_SMEM 41984

__global__ void __launch_bounds__(128, 4) k_mlp_mma(
    const int* __restrict__ exec_act_idx, float* __restrict__ out, int T) {

    extern __shared__ unsigned char sm8[];
    const uint32_t smb = smem_u32(sm8);
    const float* smallf = (const float*)(sm8 + 24576);
    const uint4* w2f = (const uint4*)sm8;                       // [kt*8+nt][lane]
    const uint4* w3f = (const uint4*)(sm8 + 16384);             // [kt*4+nt][lane]

    const int tid  = threadIdx.x;
    const int warp = tid >> 5;
    const int lane = tid & 31;
    const int q    = lane & 3;
    const int qr   = lane >> 2;
    const int rbase = warp * 32;

    // ---- copy prepped weights + smalls (25600 B) ----
    {
        const uint4* src = (const uint4*)g_wblob;
        uint4* dst = (uint4*)sm8;
        #pragma unroll
        for (int it = 0; it < 13; it++) {
            int i = tid + it * 128;
            if (i < 1600) dst[i] = src[i];
        }
    }
    __syncthreads();

    const int t  = blockIdx.x * 128 + tid;
    const int tt = (t < T) ? t : (T - 1);

    // ---- layer 1: h1 = relu(base1[j] + kf*W1L) -> fp16 -> smem A ----
    {
        int j   = g_rowjob[tt];
        float kf = (float)exec_act_idx[tt] * (1.0f / (float)NUM_EXEC);
        const float4* bp = (const float4*)(g_base1 + (size_t)j * 64);
        const int row = tid;
        #pragma unroll
        for (int c = 0; c < 8; c++) {
            float4 va = bp[2 * c];
            float4 vb = bp[2 * c + 1];
            float v0 = fmaxf(fmaf(kf, smallf[8 * c + 0], va.x), 0.0f);
            float v1 = fmaxf(fmaf(kf, smallf[8 * c + 1], va.y), 0.0f);
            float v2 = fmaxf(fmaf(kf, smallf[8 * c + 2], va.z), 0.0f);
            float v3 = fmaxf(fmaf(kf, smallf[8 * c + 3], va.w), 0.0f);
            float v4 = fmaxf(fmaf(kf, smallf[8 * c + 4], vb.x), 0.0f);
            float v5 = fmaxf(fmaf(kf, smallf[8 * c + 5], vb.y), 0.0f);
            float v6 = fmaxf(fmaf(kf, smallf[8 * c + 6], vb.z), 0.0f);
            float v7 = fmaxf(fmaf(kf, smallf[8 * c + 7], vb.w), 0.0f);
            uint4 w = make_uint4(packh2(v0, v1), packh2(v2, v3),
                                 packh2(v4, v5), packh2(v6, v7));
            uint32_t off = row * 128 + ((c ^ (row & 7)) << 4);
            *(uint4*)(sm8 + SM_A + off) = w;
        }
    }
    __syncthreads();

    // ---- layer 2: C[128,64] = Ah @ (W2h + W2l) ----
    float acc2[2][8][4];
    #pragma unroll
    for (int mt = 0; mt < 2; mt++)
        #pragma unroll
        for (int nt = 0; nt < 8; nt++)
            #pragma unroll
            for (int e = 0; e < 4; e++) acc2[mt][nt][e] = 0.0f;

    #pragma unroll
    for (int kt = 0; kt < 4; kt++) {
        uint32_t ah[2][4];
        #pragma unroll
        for (int mt = 0; mt < 2; mt++) {
            int r = rbase + mt * 16 + (lane & 15);
            uint32_t cb = kt * 32 + ((lane >> 4) << 4);
            uint32_t off = r * 128 + (cb ^ ((r & 7) << 4));
            ldmatrix4(ah[mt][0], ah[mt][1], ah[mt][2], ah[mt][3], smb + SM_A + off);
        }
        #pragma unroll
        for (int nt = 0; nt < 8; nt++) {
            uint4 b = w2f[(kt * 8 + nt) * 32 + lane];
            #pragma unroll
            for (int mt = 0; mt < 2; mt++) {
                float* d = acc2[mt][nt];
                mma16816(d[0], d[1], d[2], d[3], ah[mt][0], ah[mt][1], ah[mt][2], ah[mt][3], b.x, b.y);
                mma16816(d[0], d[1], d[2], d[3], ah[mt][0], ah[mt][1], ah[mt][2], ah[mt][3], b.z, b.w);
            }
        }
    }
    __syncthreads();   // all A reads done before overwrite

    // ---- epilogue L2: h2 = relu(C + b2) -> fp16 -> smem A ----
    #pragma unroll
    for (int mt = 0; mt < 2; mt++) {
        int r0 = rbase + mt * 16 + qr;
        #pragma unroll
        for (int nt = 0; nt < 8; nt++) {
            int cn = nt * 8 + 2 * q;
            float bb0 = smallf[64 + cn], bb1 = smallf[64 + cn + 1];
            float v0 = fmaxf(acc2[mt][nt][0] + bb0, 0.0f);
            float v1 = fmaxf(acc2[mt][nt][1] + bb1, 0.0f);
            float v2 = fmaxf(acc2[mt][nt][2] + bb0, 0.0f);
            float v3 = fmaxf(acc2[mt][nt][3] + bb1, 0.0f);
            uint32_t oa = sw128((uint32_t)(r0 * 128 + cn * 2));
            uint32_t ob = sw128((uint32_t)((r0 + 8) * 128 + cn * 2));
            *(uint32_t*)(sm8 + SM_A + oa) = packh2(v0, v1);
            *(uint32_t*)(sm8 + SM_A + ob) = packh2(v2, v3);
        }
    }
    __syncthreads();

    // ---- layer 3: C[128,32] = Ah @ (W3h + W3l) ----
    float acc3[2][4][4];
    #pragma unroll
    for (int mt = 0; mt < 2; mt++)
        #pragma unroll
        for (int nt = 0; nt < 4; nt++)
            #pragma unroll
            for (int e = 0; e < 4; e++) acc3[mt][nt][e] = 0.0f;

    #pragma unroll
    for (int kt = 0; kt < 4; kt++) {
        uint32_t ah[2][4];
        #pragma unroll
        for (int mt = 0; mt < 2; mt++) {
            int r = rbase + mt * 16 + (lane & 15);
            uint32_t cb = kt * 32 + ((lane >> 4) << 4);
            uint32_t off = r * 128 + (cb ^ ((r & 7) << 4));
            ldmatrix4(ah[mt][0], ah[mt][1], ah[mt][2], ah[mt][3], smb + SM_A + off);
        }
        #pragma unroll
        for (int nt = 0; nt < 4; nt++) {
            uint4 b = w3f[(kt * 4 + nt) * 32 + lane];
            #pragma unroll
            for (int mt = 0; mt < 2; mt++) {
                float* d = acc3[mt][nt];
                mma16816(d[0], d[1], d[2], d[3], ah[mt][0], ah[mt][1], ah[mt][2], ah[mt][3], b.x, b.y);
                mma16816(d[0], d[1], d[2], d[3], ah[mt][0], ah[mt][1], ah[mt][2], ah[mt][3], b.z, b.w);
            }
        }
    }

    // ---- epilogue L3: relu(C + b3) . W4, quad reduce, write ----
    #pragma unroll
    for (int mt = 0; mt < 2; mt++) {
        float sa = 0.0f, sb = 0.0f;
        #pragma unroll
        for (int nt = 0; nt < 4; nt++) {
            int cn = nt * 8 + 2 * q;
            float b0 = smallf[128 + cn], b1 = smallf[128 + cn + 1];
            float w0 = smallf[160 + cn], w1 = smallf[160 + cn + 1];
            sa = fmaf(fmaxf(acc3[mt][nt][0] + b0, 0.0f), w0, sa);
            sa = fmaf(fmaxf(acc3[mt][nt][1] + b1, 0.0f), w1, sa);
            sb = fmaf(fmaxf(acc3[mt][nt][2] + b0, 0.0f), w0, sb);
            sb = fmaf(fmaxf(acc3[mt][nt][3] + b1, 0.0f), w1, sb);
        }
        sa += __shfl_xor_sync(0xFFFFFFFFu, sa, 1);
        sa += __shfl_xor_sync(0xFFFFFFFFu, sa, 2);
        sb += __shfl_xor_sync(0xFFFFFFFFu, sb, 1);
        sb += __shfl_xor_sync(0xFFFFFFFFu, sb, 2);
        if (q == 0) {
            int ra = blockIdx.x * 128 + rbase + mt * 16 + qr;
            float b4v = smallf[192];
            if (ra < T)     out[ra]     = sa + b4v;
            if (ra + 8 < T) out[ra + 8] = sb + b4v;
        }
    }
}

// ================= launcher =================
extern "C" void kernel_launch(void* const* d_in, const int* in_sizes, int n_in,
                              void* d_out, int out_size) {
    const float* x          = (const float*)d_in[0];
    const float* h_dag      = (const float*)d_in[1];
    const float* h_glob     = (const float*)d_in[2];
    const int* ptr          = (const int*)d_in[3];
    const int* job_idx      = (const int*)d_in[4];
    const int* num_exec     = (const int*)d_in[5];
    const int* exec_aidx    = (const int*)d_in[6];
    const float* W1 = (const float*)d_in[7];
    const float* b1 = (const float*)d_in[8];
    const float* W2 = (const float*)d_in[9];
    const float* b2 = (const float*)d_in[10];
    const float* W3 = (const float*)d_in[11];
    const float* b3 = (const float*)d_in[12];
    const float* W4 = (const float*)d_in[13];
    const float* b4 = (const float*)d_in[14];
    float* out = (float*)d_out;

    int J = in_sizes[4];
    int T = in_sizes[6];

    cudaFuncSetAttribute(k_mlp_mma, cudaFuncAttributeMaxDynamicSharedMemorySize, KM_SMEM);

    int nblocks256 = (J + 255) / 256;

    k_p1<<<nblocks256, 256>>>(job_idx, num_exec, J);
    k_scan<<<1, 512>>>(nblocks256);
    k_p3<<<nblocks256, 256>>>(J);
    k_base1<<<(J + 63) / 64, 256>>>(x, h_dag, h_glob, ptr, job_idx, W1, b1, J);
    k_wprep<<<7, 256>>>(W1, W2, b2, W3, b3, W4, b4);
    k_mlp_mma<<<(T + 127) / 128, 128, KM_SMEM>>>(exec_aidx, out, T);
}

// round 11
// speedup vs baseline: 1.2807x; 1.1937x over previous
#include <cuda_runtime.h>
#include <cuda_fp16.h>
#include <stdint.h>

// ---------------- problem constants ----------------
#define NUM_EXEC   50
#define MAXB       60000
#define MAXT       (MAXB * NUM_EXEC)

typedef unsigned long long ull;

// ---------------- device scratch ----------------
__device__ int   g_nsel[MAXB];
__device__ int   g_blocksum[512];
__device__ int   g_rowjob[MAXT];
__device__ float g_base1[(size_t)MAXB * 64];
// prepped weight blob (exact smem image), FRAGMENT-ORDERED B, pure fp16:
//  [0,8192)      W2 frags: kt(4) x nt(8) x lane(32): uint2 {b0,b1}
//  [8192,12288)  W3 frags: kt(4) x nt(4) x lane(32): uint2
//  [12288,13312) fp32 smalls: W1L[64] b2[64] b3[32] W4[32] b4[1]
__device__ __align__(16) unsigned char g_wblob[13312];

// ---------------- helpers ----------------
__device__ __forceinline__ ull fma2(ull a, ull b, ull c) {
    ull d;
    asm("fma.rn.f32x2 %0, %1, %2, %3;" : "=l"(d) : "l"(a), "l"(b), "l"(c));
    return d;
}
__device__ __forceinline__ ull pack2(float a, float b) {
    ull r;
    asm("mov.b64 %0, {%1,%2};" : "=l"(r) : "f"(a), "f"(b));
    return r;
}
__device__ __forceinline__ void unpack2(ull v, float& a, float& b) {
    asm("mov.b64 {%0,%1}, %2;" : "=f"(a), "=f"(b) : "l"(v));
}
__device__ __forceinline__ uint32_t smem_u32(const void* p) {
    uint32_t a;
    asm("{ .reg .u64 t; cvta.to.shared.u64 t, %1; cvt.u32.u64 %0, t; }" : "=r"(a) : "l"(p));
    return a;
}
// pack (lo_elem, hi_elem) -> f16x2, lo_elem in low 16 bits
__device__ __forceinline__ uint32_t packh2(float lov, float hiv) {
    uint32_t r;
    asm("cvt.rn.f16x2.f32 %0, %1, %2;" : "=r"(r) : "f"(hiv), "f"(lov));
    return r;
}
__device__ __forceinline__ void ldmatrix4(uint32_t& a0, uint32_t& a1, uint32_t& a2,
                                          uint32_t& a3, uint32_t addr) {
    asm volatile("ldmatrix.sync.aligned.m8n8.x4.shared.b16 {%0,%1,%2,%3}, [%4];"
                 : "=r"(a0), "=r"(a1), "=r"(a2), "=r"(a3) : "r"(addr));
}
__device__ __forceinline__ void mma16816(float& d0, float& d1, float& d2, float& d3,
                                         uint32_t a0, uint32_t a1, uint32_t a2, uint32_t a3,
                                         uint32_t b0, uint32_t b1) {
    asm volatile("mma.sync.aligned.m16n8k16.row.col.f32.f16.f16.f32 "
                 "{%0,%1,%2,%3}, {%4,%5,%6,%7}, {%8,%9}, {%0,%1,%2,%3};"
                 : "+f"(d0), "+f"(d1), "+f"(d2), "+f"(d3)
                 : "r"(a0), "r"(a1), "r"(a2), "r"(a3), "r"(b0), "r"(b1));
}
// XOR-16B swizzle for 128B rows (A tile only)
__device__ __host__ __forceinline__ uint32_t sw128(uint32_t b) {
    return b ^ ((b >> 3) & 0x70);
}

// ================= prologue 1: nsel gather + per-256 block sums =================
__global__ void k_p1(const int* __restrict__ job_indices,
                     const int* __restrict__ num_exec_acts, int J) {
    __shared__ int s[256];
    int j = blockIdx.x * 256 + threadIdx.x;
    int v = 0;
    if (j < J) { v = num_exec_acts[job_indices[j]]; g_nsel[j] = v; }
    s[threadIdx.x] = v;
    __syncthreads();
    #pragma unroll
    for (int o = 128; o > 0; o >>= 1) {
        if (threadIdx.x < o) s[threadIdx.x] += s[threadIdx.x + o];
        __syncthreads();
    }
    if (threadIdx.x == 0) g_blocksum[blockIdx.x] = s[0];
}

// ================= prologue 2: exclusive scan of block sums =================
__global__ void k_scan(int nblocks) {
    __shared__ int s[512];
    int tid = threadIdx.x;
    int v = (tid < nblocks) ? g_blocksum[tid] : 0;
    s[tid] = v;
    __syncthreads();
    for (int o = 1; o < 512; o <<= 1) {
        int t = (tid >= o) ? s[tid - o] : 0;
        __syncthreads();
        s[tid] += t;
        __syncthreads();
    }
    if (tid < nblocks) g_blocksum[tid] = s[tid] - v;
}

// ================= prologue 3: per-job start + row->job fill =================
__global__ void k_p3(int J) {
    __shared__ int s[256];
    int tid = threadIdx.x;
    int j = blockIdx.x * 256 + tid;
    int v = (j < J) ? g_nsel[j] : 0;
    s[tid] = v;
    __syncthreads();
    for (int o = 1; o < 256; o <<= 1) {
        int t = (tid >= o) ? s[tid - o] : 0;
        __syncthreads();
        s[tid] += t;
        __syncthreads();
    }
    if (j < J) {
        int start = (s[tid] - v) + g_blocksum[blockIdx.x];
        for (int k = 0; k < v; k++) g_rowjob[start + k] = j;
    }
}

// ================= prologue 4: base1 — 64 jobs/block, 2 jobs + 2 acc chains ==========
__global__ void __launch_bounds__(256) k_base1(
    const float* __restrict__ x, const float* __restrict__ h_dag,
    const float* __restrict__ h_glob,
    const int* __restrict__ ptr, const int* __restrict__ jidx,
    const float* __restrict__ W1, const float* __restrict__ b1, int J) {
    __shared__ __align__(16) float sW1[35 * 64];
    __shared__ __align__(16) float sB1[64];
    for (int i = threadIdx.x; i < 35 * 64; i += blockDim.x) sW1[i] = W1[i];
    for (int i = threadIdx.x; i < 64; i += blockDim.x)      sB1[i] = b1[i];
    __syncthreads();

    const int warp = threadIdx.x >> 5;
    const int lane = threadIdx.x & 31;
    const int jbase = blockIdx.x * 64 + warp;

    #pragma unroll 1
    for (int it = 0; it < 4; it++) {
        int j0 = jbase + it * 16;
        if (j0 >= J) break;
        int j1 = j0 + 8;
        bool has1 = (j1 < J);
        int j1c = has1 ? j1 : j0;

        int ji0 = jidx[j0], ji1 = jidx[j1c];
        const float* xr0 = x + (long long)ptr[ji0] * 5;
        const float* xr1 = x + (long long)ptr[ji1] * 5;
        const float* hd0 = h_dag + (long long)ji0 * 16;
        const float* hd1 = h_dag + (long long)ji1 * 16;
        const float* hg0 = h_glob + (long long)j0 * 16;
        const float* hg1 = h_glob + (long long)j1c * 16;

        ull bias = pack2(sB1[2 * lane], sB1[2 * lane + 1]);
        ull zero = pack2(0.0f, 0.0f);
        ull a0A = bias, a0B = zero;
        ull a1A = bias, a1B = zero;

        #pragma unroll
        for (int i = 0; i < 3; i++) {
            ull w = *(const ull*)&sW1[i * 64 + 2 * lane];
            float v0 = xr0[i], v1 = xr1[i];
            a0A = fma2(pack2(v0, v0), w, a0A);
            a1A = fma2(pack2(v1, v1), w, a1A);
        }
        #pragma unroll
        for (int i = 0; i < 16; i++) {
            ull w = *(const ull*)&sW1[(3 + i) * 64 + 2 * lane];
            float v0 = hd0[i], v1 = hd1[i];
            if (i & 1) { a0B = fma2(pack2(v0, v0), w, a0B); a1B = fma2(pack2(v1, v1), w, a1B); }
            else       { a0A = fma2(pack2(v0, v0), w, a0A); a1A = fma2(pack2(v1, v1), w, a1A); }
        }
        #pragma unroll
        for (int i = 0; i < 16; i++) {
            ull w = *(const ull*)&sW1[(19 + i) * 64 + 2 * lane];
            float v0 = hg0[i], v1 = hg1[i];
            if (i & 1) { a0B = fma2(pack2(v0, v0), w, a0B); a1B = fma2(pack2(v1, v1), w, a1B); }
            else       { a0A = fma2(pack2(v0, v0), w, a0A); a1A = fma2(pack2(v1, v1), w, a1A); }
        }

        float xa, xb, ya, yb;
        unpack2(a0A, xa, xb);
        unpack2(a0B, ya, yb);
        float* d0 = g_base1 + (size_t)j0 * 64 + 2 * lane;
        d0[0] = xa + ya;
        d0[1] = xb + yb;
        if (has1) {
            unpack2(a1A, xa, xb);
            unpack2(a1B, ya, yb);
            float* d1 = g_base1 + (size_t)j1 * 64 + 2 * lane;
            d1[0] = xa + ya;
            d1[1] = xb + yb;
        }
    }
}

// ================= prologue 5: weight prep — FRAGMENT-ORDERED pure fp16 ==========
// Each (kt, nt, lane) thread emits uint2 {b0, b1}:
//   q = lane&3, qr = lane>>2, n = nt*8 + qr
//   k0 = kt*16 + 2q:  b0 = f16x2(W[k0][n], W[k0+1][n]), b1 = f16x2(W[k0+8][n], W[k0+9][n])
__global__ void k_wprep(const float* __restrict__ W1, const float* __restrict__ W2,
                        const float* __restrict__ b2, const float* __restrict__ W3,
                        const float* __restrict__ b3, const float* __restrict__ W4,
                        const float* __restrict__ b4) {
    int tid = blockIdx.x * blockDim.x + threadIdx.x;
    if (tid < 1024) {                 // W2 fragments: kt(4) x nt(8) x lane(32)
        int kt = tid >> 8, nt = (tid >> 5) & 7, lane = tid & 31;
        int q = lane & 3, qr = lane >> 2;
        int n = nt * 8 + qr;
        int k0 = kt * 16 + 2 * q;
        uint2 v;
        v.x = packh2(W2[(k0    ) * 64 + n], W2[(k0 + 1) * 64 + n]);
        v.y = packh2(W2[(k0 + 8) * 64 + n], W2[(k0 + 9) * 64 + n]);
        ((uint2*)g_wblob)[tid] = v;
    } else if (tid < 1536) {          // W3 fragments: kt(4) x nt(4) x lane(32)
        int e = tid - 1024;
        int kt = e >> 7, nt = (e >> 5) & 3, lane = e & 31;
        int q = lane & 3, qr = lane >> 2;
        int n = nt * 8 + qr;
        int k0 = kt * 16 + 2 * q;
        uint2 v;
        v.x = packh2(W3[(k0    ) * 32 + n], W3[(k0 + 1) * 32 + n]);
        v.y = packh2(W3[(k0 + 8) * 32 + n], W3[(k0 + 9) * 32 + n]);
        ((uint2*)g_wblob)[1024 + e] = v;
    } else if (tid < 1536 + 256) {
        int i = tid - 1536;
        float* s = (float*)(g_wblob + 12288);
        if (i < 64)       s[i] = W1[35 * 64 + i];
        else if (i < 128) s[i] = b2[i - 64];
        else if (i < 160) s[i] = b3[i - 128];
        else if (i < 192) s[i] = W4[i - 160];
        else if (i == 192) s[192] = b4[0];
    }
}

// ================= main: mma.sync pure-fp16 W, frag-ordered B, 128 rows/CTA ====
// dyn smem: [0,13312) weight blob image; [13312,29696) A fp16 [128][128B] swizzled
#define SM_A    13312
#define KM_SMEM 29696

__global__ void __launch_bounds__(128, 6) k_mlp_mma(
    const int* __restrict__ exec_act_idx, float* __restrict__ out, int T) {

    extern __shared__ unsigned char sm8[];
    const uint32_t smb = smem_u32(sm8);
    const float* smallf = (const float*)(sm8 + 12288);
    const uint2* w2f = (const uint2*)sm8;                       // [kt*8+nt][lane]
    const uint2* w3f = (const uint2*)(sm8 + 8192);              // [kt*4+nt][lane]

    const int tid  = threadIdx.x;
    const int warp = tid >> 5;
    const int lane = tid & 31;
    const int q    = lane & 3;
    const int qr   = lane >> 2;
    const int rbase = warp * 32;

    // ---- copy prepped weights + smalls (13312 B = 832 uint4) ----
    {
        const uint4* src = (const uint4*)g_wblob;
        uint4* dst = (uint4*)sm8;
        #pragma unroll
        for (int it = 0; it < 7; it++) {
            int i = tid + it * 128;
            if (i < 832) dst[i] = src[i];
        }
    }
    __syncthreads();

    const int t  = blockIdx.x * 128 + tid;
    const int tt = (t < T) ? t : (T - 1);

    // ---- layer 1: h1 = relu(base1[j] + kf*W1L) -> fp16 -> smem A ----
    {
        int j   = g_rowjob[tt];
        float kf = (float)exec_act_idx[tt] * (1.0f / (float)NUM_EXEC);
        const float4* bp = (const float4*)(g_base1 + (size_t)j * 64);
        const int row = tid;
        #pragma unroll
        for (int c = 0; c < 8; c++) {
            float4 va = bp[2 * c];
            float4 vb = bp[2 * c + 1];
            float v0 = fmaxf(fmaf(kf, smallf[8 * c + 0], va.x), 0.0f);
            float v1 = fmaxf(fmaf(kf, smallf[8 * c + 1], va.y), 0.0f);
            float v2 = fmaxf(fmaf(kf, smallf[8 * c + 2], va.z), 0.0f);
            float v3 = fmaxf(fmaf(kf, smallf[8 * c + 3], va.w), 0.0f);
            float v4 = fmaxf(fmaf(kf, smallf[8 * c + 4], vb.x), 0.0f);
            float v5 = fmaxf(fmaf(kf, smallf[8 * c + 5], vb.y), 0.0f);
            float v6 = fmaxf(fmaf(kf, smallf[8 * c + 6], vb.z), 0.0f);
            float v7 = fmaxf(fmaf(kf, smallf[8 * c + 7], vb.w), 0.0f);
            uint4 w = make_uint4(packh2(v0, v1), packh2(v2, v3),
                                 packh2(v4, v5), packh2(v6, v7));
            uint32_t off = row * 128 + ((c ^ (row & 7)) << 4);
            *(uint4*)(sm8 + SM_A + off) = w;
        }
    }
    __syncthreads();

    // ---- layer 2: C[128,64] = Ah @ W2h ----
    float acc2[2][8][4];
    #pragma unroll
    for (int mt = 0; mt < 2; mt++)
        #pragma unroll
        for (int nt = 0; nt < 8; nt++)
            #pragma unroll
            for (int e = 0; e < 4; e++) acc2[mt][nt][e] = 0.0f;

    #pragma unroll
    for (int kt = 0; kt < 4; kt++) {
        uint32_t ah[2][4];
        #pragma unroll
        for (int mt = 0; mt < 2; mt++) {
            int r = rbase + mt * 16 + (lane & 15);
            uint32_t cb = kt * 32 + ((lane >> 4) << 4);
            uint32_t off = r * 128 + (cb ^ ((r & 7) << 4));
            ldmatrix4(ah[mt][0], ah[mt][1], ah[mt][2], ah[mt][3], smb + SM_A + off);
        }
        #pragma unroll
        for (int nt = 0; nt < 8; nt++) {
            uint2 b = w2f[(kt * 8 + nt) * 32 + lane];
            #pragma unroll
            for (int mt = 0; mt < 2; mt++) {
                float* d = acc2[mt][nt];
                mma16816(d[0], d[1], d[2], d[3], ah[mt][0], ah[mt][1], ah[mt][2], ah[mt][3], b.x, b.y);
            }
        }
    }
    __syncthreads();   // all A reads done before overwrite

    // ---- epilogue L2: h2 = relu(C + b2) -> fp16 -> smem A ----
    #pragma unroll
    for (int mt = 0; mt < 2; mt++) {
        int r0 = rbase + mt * 16 + qr;
        #pragma unroll
        for (int nt = 0; nt < 8; nt++) {
            int cn = nt * 8 + 2 * q;
            float bb0 = smallf[64 + cn], bb1 = smallf[64 + cn + 1];
            float v0 = fmaxf(acc2[mt][nt][0] + bb0, 0.0f);
            float v1 = fmaxf(acc2[mt][nt][1] + bb1, 0.0f);
            float v2 = fmaxf(acc2[mt][nt][2] + bb0, 0.0f);
            float v3 = fmaxf(acc2[mt][nt][3] + bb1, 0.0f);
            uint32_t oa = sw128((uint32_t)(r0 * 128 + cn * 2));
            uint32_t ob = sw128((uint32_t)((r0 + 8) * 128 + cn * 2));
            *(uint32_t*)(sm8 + SM_A + oa) = packh2(v0, v1);
            *(uint32_t*)(sm8 + SM_A + ob) = packh2(v2, v3);
        }
    }
    __syncthreads();

    // ---- layer 3: C[128,32] = Ah @ W3h ----
    float acc3[2][4][4];
    #pragma unroll
    for (int mt = 0; mt < 2; mt++)
        #pragma unroll
        for (int nt = 0; nt < 4; nt++)
            #pragma unroll
            for (int e = 0; e < 4; e++) acc3[mt][nt][e] = 0.0f;

    #pragma unroll
    for (int kt = 0; kt < 4; kt++) {
        uint32_t ah[2][4];
        #pragma unroll
        for (int mt = 0; mt < 2; mt++) {
            int r = rbase + mt * 16 + (lane & 15);
            uint32_t cb = kt * 32 + ((lane >> 4) << 4);
            uint32_t off = r * 128 + (cb ^ ((r & 7) << 4));
            ldmatrix4(ah[mt][0], ah[mt][1], ah[mt][2], ah[mt][3], smb + SM_A + off);
        }
        #pragma unroll
        for (int nt = 0; nt < 4; nt++) {
            uint2 b = w3f[(kt * 4 + nt) * 32 + lane];
            #pragma unroll
            for (int mt = 0; mt < 2; mt++) {
                float* d = acc3[mt][nt];
                mma16816(d[0], d[1], d[2], d[3], ah[mt][0], ah[mt][1], ah[mt][2], ah[mt][3], b.x, b.y);
            }
        }
    }

    // ---- epilogue L3: relu(C + b3) . W4, quad reduce, write ----
    #pragma unroll
    for (int mt = 0; mt < 2; mt++) {
        float sa = 0.0f, sb = 0.0f;
        #pragma unroll
        for (int nt = 0; nt < 4; nt++) {
            int cn = nt * 8 + 2 * q;
            float b0 = smallf[128 + cn], b1 = smallf[128 + cn + 1];
            float w0 = smallf[160 + cn], w1 = smallf[160 + cn + 1];
            sa = fmaf(fmaxf(acc3[mt][nt][0] + b0, 0.0f), w0, sa);
            sa = fmaf(fmaxf(acc3[mt][nt][1] + b1, 0.0f), w1, sa);
            sb = fmaf(fmaxf(acc3[mt][nt][2] + b0, 0.0f), w0, sb);
            sb = fmaf(fmaxf(acc3[mt][nt][3] + b1, 0.0f), w1, sb);
        }
        sa += __shfl_xor_sync(0xFFFFFFFFu, sa, 1);
        sa += __shfl_xor_sync(0xFFFFFFFFu, sa, 2);
        sb += __shfl_xor_sync(0xFFFFFFFFu, sb, 1);
        sb += __shfl_xor_sync(0xFFFFFFFFu, sb, 2);
        if (q == 0) {
            int ra = blockIdx.x * 128 + rbase + mt * 16 + qr;
            float b4v = smallf[192];
            if (ra < T)     out[ra]     = sa + b4v;
            if (ra + 8 < T) out[ra + 8] = sb + b4v;
        }
    }
}

// ================= launcher =================
extern "C" void kernel_launch(void* const* d_in, const int* in_sizes, int n_in,
                              void* d_out, int out_size) {
    const float* x          = (const float*)d_in[0];
    const float* h_dag      = (const float*)d_in[1];
    const float* h_glob     = (const float*)d_in[2];
    const int* ptr          = (const int*)d_in[3];
    const int* job_idx      = (const int*)d_in[4];
    const int* num_exec     = (const int*)d_in[5];
    const int* exec_aidx    = (const int*)d_in[6];
    const float* W1 = (const float*)d_in[7];
    const float* b1 = (const float*)d_in[8];
    const float* W2 = (const float*)d_in[9];
    const float* b2 = (const float*)d_in[10];
    const float* W3 = (const float*)d_in[11];
    const float* b3 = (const float*)d_in[12];
    const float* W4 = (const float*)d_in[13];
    const float* b4 = (const float*)d_in[14];
    float* out = (float*)d_out;

    int J = in_sizes[4];
    int T = in_sizes[6];

    cudaFuncSetAttribute(k_mlp_mma, cudaFuncAttributeMaxDynamicSharedMemorySize, KM_SMEM);

    int nblocks256 = (J + 255) / 256;

    k_p1<<<nblocks256, 256>>>(job_idx, num_exec, J);
    k_scan<<<1, 512>>>(nblocks256);
    k_p3<<<nblocks256, 256>>>(J);
    k_base1<<<(J + 63) / 64, 256>>>(x, h_dag, h_glob, ptr, job_idx, W1, b1, J);
    k_wprep<<<7, 256>>>(W1, W2, b2, W3, b3, W4, b4);
    k_mlp_mma<<<(T + 127) / 128, 128, KM_SMEM>>>(exec_aidx, out, T);
}

// round 12
// speedup vs baseline: 1.4928x; 1.1656x over previous
#include <cuda_runtime.h>
#include <cuda_fp16.h>
#include <stdint.h>

// ---------------- problem constants ----------------
#define NUM_EXEC   50
#define MAXB       60000
#define MAXT       (MAXB * NUM_EXEC)

typedef unsigned long long ull;

// ---------------- device scratch ----------------
__device__ int   g_nsel[MAXB];
__device__ int   g_blocksum[512];
__device__ int   g_rowjob[MAXT];
__device__ float g_base1[(size_t)MAXB * 64];
// prepped weight blob (exact smem image), FRAGMENT-ORDERED B, pure fp16:
//  [0,8192)      W2 frags: kt(4) x nt(8) x lane(32): uint2 {b0,b1}
//  [8192,12288)  W3 frags: kt(4) x nt(4) x lane(32): uint2
//  [12288,13312) fp32 smalls: W1L[64] b2[64] b3[32] W4[32] b4[1]
__device__ __align__(16) unsigned char g_wblob[13312];

// ---------------- helpers ----------------
__device__ __forceinline__ ull fma2(ull a, ull b, ull c) {
    ull d;
    asm("fma.rn.f32x2 %0, %1, %2, %3;" : "=l"(d) : "l"(a), "l"(b), "l"(c));
    return d;
}
__device__ __forceinline__ ull pack2(float a, float b) {
    ull r;
    asm("mov.b64 %0, {%1,%2};" : "=l"(r) : "f"(a), "f"(b));
    return r;
}
__device__ __forceinline__ void unpack2(ull v, float& a, float& b) {
    asm("mov.b64 {%0,%1}, %2;" : "=f"(a), "=f"(b) : "l"(v));
}
__device__ __forceinline__ uint32_t smem_u32(const void* p) {
    uint32_t a;
    asm("{ .reg .u64 t; cvta.to.shared.u64 t, %1; cvt.u32.u64 %0, t; }" : "=r"(a) : "l"(p));
    return a;
}
// pack (lo_elem, hi_elem) -> f16x2, lo_elem in low 16 bits
__device__ __forceinline__ uint32_t packh2(float lov, float hiv) {
    uint32_t r;
    asm("cvt.rn.f16x2.f32 %0, %1, %2;" : "=r"(r) : "f"(hiv), "f"(lov));
    return r;
}
__device__ __forceinline__ void ldmatrix4(uint32_t& a0, uint32_t& a1, uint32_t& a2,
                                          uint32_t& a3, uint32_t addr) {
    asm volatile("ldmatrix.sync.aligned.m8n8.x4.shared.b16 {%0,%1,%2,%3}, [%4];"
                 : "=r"(a0), "=r"(a1), "=r"(a2), "=r"(a3) : "r"(addr));
}
__device__ __forceinline__ void mma16816(float& d0, float& d1, float& d2, float& d3,
                                         uint32_t a0, uint32_t a1, uint32_t a2, uint32_t a3,
                                         uint32_t b0, uint32_t b1) {
    asm volatile("mma.sync.aligned.m16n8k16.row.col.f32.f16.f16.f32 "
                 "{%0,%1,%2,%3}, {%4,%5,%6,%7}, {%8,%9}, {%0,%1,%2,%3};"
                 : "+f"(d0), "+f"(d1), "+f"(d2), "+f"(d3)
                 : "r"(a0), "r"(a1), "r"(a2), "r"(a3), "r"(b0), "r"(b1));
}
// XOR-16B swizzle for 128B rows (A tile only)
__device__ __host__ __forceinline__ uint32_t sw128(uint32_t b) {
    return b ^ ((b >> 3) & 0x70);
}

// ================= prologue 1: nsel gather + per-256 block sums =================
__global__ void k_p1(const int* __restrict__ job_indices,
                     const int* __restrict__ num_exec_acts, int J) {
    __shared__ int s[256];
    int j = blockIdx.x * 256 + threadIdx.x;
    int v = 0;
    if (j < J) { v = num_exec_acts[job_indices[j]]; g_nsel[j] = v; }
    s[threadIdx.x] = v;
    __syncthreads();
    #pragma unroll
    for (int o = 128; o > 0; o >>= 1) {
        if (threadIdx.x < o) s[threadIdx.x] += s[threadIdx.x + o];
        __syncthreads();
    }
    if (threadIdx.x == 0) g_blocksum[blockIdx.x] = s[0];
}

// ================= prologue 2: exclusive scan of block sums =================
__global__ void k_scan(int nblocks) {
    __shared__ int s[512];
    int tid = threadIdx.x;
    int v = (tid < nblocks) ? g_blocksum[tid] : 0;
    s[tid] = v;
    __syncthreads();
    for (int o = 1; o < 512; o <<= 1) {
        int t = (tid >= o) ? s[tid - o] : 0;
        __syncthreads();
        s[tid] += t;
        __syncthreads();
    }
    if (tid < nblocks) g_blocksum[tid] = s[tid] - v;
}

// ================= prologue 3: per-job start + row->job fill =================
__global__ void k_p3(int J) {
    __shared__ int s[256];
    int tid = threadIdx.x;
    int j = blockIdx.x * 256 + tid;
    int v = (j < J) ? g_nsel[j] : 0;
    s[tid] = v;
    __syncthreads();
    for (int o = 1; o < 256; o <<= 1) {
        int t = (tid >= o) ? s[tid - o] : 0;
        __syncthreads();
        s[tid] += t;
        __syncthreads();
    }
    if (j < J) {
        int start = (s[tid] - v) + g_blocksum[blockIdx.x];
        for (int k = 0; k < v; k++) g_rowjob[start + k] = j;
    }
}

// ================= prologue 4: base1 — 64 jobs/block, 2 jobs + 2 acc chains ==========
__global__ void __launch_bounds__(256) k_base1(
    const float* __restrict__ x, const float* __restrict__ h_dag,
    const float* __restrict__ h_glob,
    const int* __restrict__ ptr, const int* __restrict__ jidx,
    const float* __restrict__ W1, const float* __restrict__ b1, int J) {
    __shared__ __align__(16) float sW1[35 * 64];
    __shared__ __align__(16) float sB1[64];
    for (int i = threadIdx.x; i < 35 * 64; i += blockDim.x) sW1[i] = W1[i];
    for (int i = threadIdx.x; i < 64; i += blockDim.x)      sB1[i] = b1[i];
    __syncthreads();

    const int warp = threadIdx.x >> 5;
    const int lane = threadIdx.x & 31;
    const int jbase = blockIdx.x * 64 + warp;

    #pragma unroll 1
    for (int it = 0; it < 4; it++) {
        int j0 = jbase + it * 16;
        if (j0 >= J) break;
        int j1 = j0 + 8;
        bool has1 = (j1 < J);
        int j1c = has1 ? j1 : j0;

        int ji0 = jidx[j0], ji1 = jidx[j1c];
        const float* xr0 = x + (long long)ptr[ji0] * 5;
        const float* xr1 = x + (long long)ptr[ji1] * 5;
        const float* hd0 = h_dag + (long long)ji0 * 16;
        const float* hd1 = h_dag + (long long)ji1 * 16;
        const float* hg0 = h_glob + (long long)j0 * 16;
        const float* hg1 = h_glob + (long long)j1c * 16;

        ull bias = pack2(sB1[2 * lane], sB1[2 * lane + 1]);
        ull zero = pack2(0.0f, 0.0f);
        ull a0A = bias, a0B = zero;
        ull a1A = bias, a1B = zero;

        #pragma unroll
        for (int i = 0; i < 3; i++) {
            ull w = *(const ull*)&sW1[i * 64 + 2 * lane];
            float v0 = xr0[i], v1 = xr1[i];
            a0A = fma2(pack2(v0, v0), w, a0A);
            a1A = fma2(pack2(v1, v1), w, a1A);
        }
        #pragma unroll
        for (int i = 0; i < 16; i++) {
            ull w = *(const ull*)&sW1[(3 + i) * 64 + 2 * lane];
            float v0 = hd0[i], v1 = hd1[i];
            if (i & 1) { a0B = fma2(pack2(v0, v0), w, a0B); a1B = fma2(pack2(v1, v1), w, a1B); }
            else       { a0A = fma2(pack2(v0, v0), w, a0A); a1A = fma2(pack2(v1, v1), w, a1A); }
        }
        #pragma unroll
        for (int i = 0; i < 16; i++) {
            ull w = *(const ull*)&sW1[(19 + i) * 64 + 2 * lane];
            float v0 = hg0[i], v1 = hg1[i];
            if (i & 1) { a0B = fma2(pack2(v0, v0), w, a0B); a1B = fma2(pack2(v1, v1), w, a1B); }
            else       { a0A = fma2(pack2(v0, v0), w, a0A); a1A = fma2(pack2(v1, v1), w, a1A); }
        }

        float xa, xb, ya, yb;
        unpack2(a0A, xa, xb);
        unpack2(a0B, ya, yb);
        float* d0 = g_base1 + (size_t)j0 * 64 + 2 * lane;
        d0[0] = xa + ya;
        d0[1] = xb + yb;
        if (has1) {
            unpack2(a1A, xa, xb);
            unpack2(a1B, ya, yb);
            float* d1 = g_base1 + (size_t)j1 * 64 + 2 * lane;
            d1[0] = xa + ya;
            d1[1] = xb + yb;
        }
    }
}

// ================= prologue 5: weight prep — FRAGMENT-ORDERED pure fp16 ==========
__global__ void k_wprep(const float* __restrict__ W1, const float* __restrict__ W2,
                        const float* __restrict__ b2, const float* __restrict__ W3,
                        const float* __restrict__ b3, const float* __restrict__ W4,
                        const float* __restrict__ b4) {
    int tid = blockIdx.x * blockDim.x + threadIdx.x;
    if (tid < 1024) {                 // W2 fragments: kt(4) x nt(8) x lane(32)
        int kt = tid >> 8, nt = (tid >> 5) & 7, lane = tid & 31;
        int q = lane & 3, qr = lane >> 2;
        int n = nt * 8 + qr;
        int k0 = kt * 16 + 2 * q;
        uint2 v;
        v.x = packh2(W2[(k0    ) * 64 + n], W2[(k0 + 1) * 64 + n]);
        v.y = packh2(W2[(k0 + 8) * 64 + n], W2[(k0 + 9) * 64 + n]);
        ((uint2*)g_wblob)[tid] = v;
    } else if (tid < 1536) {          // W3 fragments: kt(4) x nt(4) x lane(32)
        int e = tid - 1024;
        int kt = e >> 7, nt = (e >> 5) & 3, lane = e & 31;
        int q = lane & 3, qr = lane >> 2;
        int n = nt * 8 + qr;
        int k0 = kt * 16 + 2 * q;
        uint2 v;
        v.x = packh2(W3[(k0    ) * 32 + n], W3[(k0 + 1) * 32 + n]);
        v.y = packh2(W3[(k0 + 8) * 32 + n], W3[(k0 + 9) * 32 + n]);
        ((uint2*)g_wblob)[1024 + e] = v;
    } else if (tid < 1536 + 256) {
        int i = tid - 1536;
        float* s = (float*)(g_wblob + 12288);
        if (i < 64)       s[i] = W1[35 * 64 + i];
        else if (i < 128) s[i] = b2[i - 64];
        else if (i < 160) s[i] = b3[i - 128];
        else if (i < 192) s[i] = W4[i - 160];
        else if (i == 192) s[192] = b4[0];
    }
}

// ================= main: mma.sync pure-fp16, register-pass L2->L3, 128 rows/CTA ====
// dyn smem: [0,13312) weight blob image; [13312,29696) A fp16 [128][128B] swizzled
#define SM_A    13312
#define KM_SMEM 29696

__global__ void __launch_bounds__(128, 5) k_mlp_mma(
    const int* __restrict__ exec_act_idx, float* __restrict__ out, int T) {

    extern __shared__ unsigned char sm8[];
    const uint32_t smb = smem_u32(sm8);
    const float* smallf = (const float*)(sm8 + 12288);
    const uint2* w2f = (const uint2*)sm8;                       // [kt*8+nt][lane]
    const uint2* w3f = (const uint2*)(sm8 + 8192);              // [kt*4+nt][lane]

    const int tid  = threadIdx.x;
    const int warp = tid >> 5;
    const int lane = tid & 31;
    const int q    = lane & 3;
    const int qr   = lane >> 2;
    const int rbase = warp * 32;

    // ---- copy prepped weights + smalls (13312 B = 832 uint4) ----
    {
        const uint4* src = (const uint4*)g_wblob;
        uint4* dst = (uint4*)sm8;
        #pragma unroll
        for (int it = 0; it < 7; it++) {
            int i = tid + it * 128;
            if (i < 832) dst[i] = src[i];
        }
    }
    __syncthreads();

    const int t  = blockIdx.x * 128 + tid;
    const int tt = (t < T) ? t : (T - 1);

    // ---- layer 1: h1 = relu(base1[j] + kf*W1L) -> fp16 -> smem A ----
    {
        int j   = g_rowjob[tt];
        float kf = (float)exec_act_idx[tt] * (1.0f / (float)NUM_EXEC);
        const float4* bp = (const float4*)(g_base1 + (size_t)j * 64);
        const int row = tid;
        #pragma unroll
        for (int c = 0; c < 8; c++) {
            float4 va = bp[2 * c];
            float4 vb = bp[2 * c + 1];
            float v0 = fmaxf(fmaf(kf, smallf[8 * c + 0], va.x), 0.0f);
            float v1 = fmaxf(fmaf(kf, smallf[8 * c + 1], va.y), 0.0f);
            float v2 = fmaxf(fmaf(kf, smallf[8 * c + 2], va.z), 0.0f);
            float v3 = fmaxf(fmaf(kf, smallf[8 * c + 3], va.w), 0.0f);
            float v4 = fmaxf(fmaf(kf, smallf[8 * c + 4], vb.x), 0.0f);
            float v5 = fmaxf(fmaf(kf, smallf[8 * c + 5], vb.y), 0.0f);
            float v6 = fmaxf(fmaf(kf, smallf[8 * c + 6], vb.z), 0.0f);
            float v7 = fmaxf(fmaf(kf, smallf[8 * c + 7], vb.w), 0.0f);
            uint4 w = make_uint4(packh2(v0, v1), packh2(v2, v3),
                                 packh2(v4, v5), packh2(v6, v7));
            uint32_t off = row * 128 + ((c ^ (row & 7)) << 4);
            *(uint4*)(sm8 + SM_A + off) = w;
        }
    }
    __syncthreads();

    // ---- layer 2: C[128,64] = Ah @ W2h ----
    float acc2[2][8][4];
    #pragma unroll
    for (int mt = 0; mt < 2; mt++)
        #pragma unroll
        for (int nt = 0; nt < 8; nt++)
            #pragma unroll
            for (int e = 0; e < 4; e++) acc2[mt][nt][e] = 0.0f;

    #pragma unroll
    for (int kt = 0; kt < 4; kt++) {
        uint32_t ah[2][4];
        #pragma unroll
        for (int mt = 0; mt < 2; mt++) {
            int r = rbase + mt * 16 + (lane & 15);
            uint32_t cb = kt * 32 + ((lane >> 4) << 4);
            uint32_t off = r * 128 + (cb ^ ((r & 7) << 4));
            ldmatrix4(ah[mt][0], ah[mt][1], ah[mt][2], ah[mt][3], smb + SM_A + off);
        }
        #pragma unroll
        for (int nt = 0; nt < 8; nt++) {
            uint2 b = w2f[(kt * 8 + nt) * 32 + lane];
            #pragma unroll
            for (int mt = 0; mt < 2; mt++) {
                float* d = acc2[mt][nt];
                mma16816(d[0], d[1], d[2], d[3], ah[mt][0], ah[mt][1], ah[mt][2], ah[mt][3], b.x, b.y);
            }
        }
    }

    // ---- register epilogue L2 + fragment pack: h2 = relu(C+b2) -> A fragments ----
    // C frag (qr,2q),(qr,2q+1),(qr+8,2q),(qr+8,2q+1) of tile nt maps to A frag regs:
    //   nt = 2kt   -> a0 = packh2(v0,v1), a1 = packh2(v2,v3)
    //   nt = 2kt+1 -> a2 = packh2(v0,v1), a3 = packh2(v2,v3)
    uint32_t a3f[2][4][4];   // [mt][kt][reg]
    #pragma unroll
    for (int mt = 0; mt < 2; mt++) {
        #pragma unroll
        for (int nt = 0; nt < 8; nt++) {
            int cn = nt * 8 + 2 * q;
            float bb0 = smallf[64 + cn], bb1 = smallf[64 + cn + 1];
            float v0 = fmaxf(acc2[mt][nt][0] + bb0, 0.0f);
            float v1 = fmaxf(acc2[mt][nt][1] + bb1, 0.0f);
            float v2 = fmaxf(acc2[mt][nt][2] + bb0, 0.0f);
            float v3 = fmaxf(acc2[mt][nt][3] + bb1, 0.0f);
            int kt = nt >> 1;
            int h  = (nt & 1) << 1;
            a3f[mt][kt][h + 0] = packh2(v0, v1);
            a3f[mt][kt][h + 1] = packh2(v2, v3);
        }
    }

    // ---- layer 3: C[128,32] = Ah @ W3h (A from registers) ----
    float acc3[2][4][4];
    #pragma unroll
    for (int mt = 0; mt < 2; mt++)
        #pragma unroll
        for (int nt = 0; nt < 4; nt++)
            #pragma unroll
            for (int e = 0; e < 4; e++) acc3[mt][nt][e] = 0.0f;

    #pragma unroll
    for (int kt = 0; kt < 4; kt++) {
        #pragma unroll
        for (int nt = 0; nt < 4; nt++) {
            uint2 b = w3f[(kt * 4 + nt) * 32 + lane];
            #pragma unroll
            for (int mt = 0; mt < 2; mt++) {
                float* d = acc3[mt][nt];
                mma16816(d[0], d[1], d[2], d[3],
                         a3f[mt][kt][0], a3f[mt][kt][1], a3f[mt][kt][2], a3f[mt][kt][3],
                         b.x, b.y);
            }
        }
    }

    // ---- epilogue L3: relu(C + b3) . W4, quad reduce, write ----
    #pragma unroll
    for (int mt = 0; mt < 2; mt++) {
        float sa = 0.0f, sb = 0.0f;
        #pragma unroll
        for (int nt = 0; nt < 4; nt++) {
            int cn = nt * 8 + 2 * q;
            float b0 = smallf[128 + cn], b1 = smallf[128 + cn + 1];
            float w0 = smallf[160 + cn], w1 = smallf[160 + cn + 1];
            sa = fmaf(fmaxf(acc3[mt][nt][0] + b0, 0.0f), w0, sa);
            sa = fmaf(fmaxf(acc3[mt][nt][1] + b1, 0.0f), w1, sa);
            sb = fmaf(fmaxf(acc3[mt][nt][2] + b0, 0.0f), w0, sb);
            sb = fmaf(fmaxf(acc3[mt][nt][3] + b1, 0.0f), w1, sb);
        }
        sa += __shfl_xor_sync(0xFFFFFFFFu, sa, 1);
        sa += __shfl_xor_sync(0xFFFFFFFFu, sa, 2);
        sb += __shfl_xor_sync(0xFFFFFFFFu, sb, 1);
        sb += __shfl_xor_sync(0xFFFFFFFFu, sb, 2);
        if (q == 0) {
            int ra = blockIdx.x * 128 + rbase + mt * 16 + qr;
            float b4v = smallf[192];
            if (ra < T)     out[ra]     = sa + b4v;
            if (ra + 8 < T) out[ra + 8] = sb + b4v;
        }
    }
}

// ================= launcher =================
extern "C" void kernel_launch(void* const* d_in, const int* in_sizes, int n_in,
                              void* d_out, int out_size) {
    const float* x          = (const float*)d_in[0];
    const float* h_dag      = (const float*)d_in[1];
    const float* h_glob     = (const float*)d_in[2];
    const int* ptr          = (const int*)d_in[3];
    const int* job_idx      = (const int*)d_in[4];
    const int* num_exec     = (const int*)d_in[5];
    const int* exec_aidx    = (const int*)d_in[6];
    const float* W1 = (const float*)d_in[7];
    const float* b1 = (const float*)d_in[8];
    const float* W2 = (const float*)d_in[9];
    const float* b2 = (const float*)d_in[10];
    const float* W3 = (const float*)d_in[11];
    const float* b3 = (const float*)d_in[12];
    const float* W4 = (const float*)d_in[13];
    const float* b4 = (const float*)d_in[14];
    float* out = (float*)d_out;

    int J = in_sizes[4];
    int T = in_sizes[6];

    cudaFuncSetAttribute(k_mlp_mma, cudaFuncAttributeMaxDynamicSharedMemorySize, KM_SMEM);

    int nblocks256 = (J + 255) / 256;

    k_p1<<<nblocks256, 256>>>(job_idx, num_exec, J);
    k_scan<<<1, 512>>>(nblocks256);
    k_p3<<<nblocks256, 256>>>(J);
    k_base1<<<(J + 63) / 64, 256>>>(x, h_dag, h_glob, ptr, job_idx, W1, b1, J);
    k_wprep<<<7, 256>>>(W1, W2, b2, W3, b3, W4, b4);
    k_mlp_mma<<<(T + 127) / 128, 128, KM_SMEM>>>(exec_aidx, out, T);
}